// round 9
// baseline (speedup 1.0000x reference)
#include <cuda_runtime.h>
#include <cuda_bf16.h>
#include <cstdint>
#include <cstddef>

#define EPSV 1e-5f

__device__ __forceinline__ uint32_t smem_to_u32(const void* p) {
    uint32_t a;
    asm("{ .reg .u64 t; cvta.to.shared.u64 t, %1; cvt.u32.u64 %0, t; }" : "=r"(a) : "l"(p));
    return a;
}
__device__ __forceinline__ void ldsm4(uint32_t* r, uint32_t addr) {
    asm volatile("ldmatrix.sync.aligned.m8n8.x4.shared.b16 {%0,%1,%2,%3}, [%4];"
        : "=r"(r[0]), "=r"(r[1]), "=r"(r[2]), "=r"(r[3]) : "r"(addr));
}
__device__ __forceinline__ void mma_bf16(float* d, const uint32_t* a, uint32_t b0, uint32_t b1) {
    asm volatile("mma.sync.aligned.m16n8k16.row.col.f32.bf16.bf16.f32 "
        "{%0,%1,%2,%3}, {%4,%5,%6,%7}, {%8,%9}, {%0,%1,%2,%3};"
        : "+f"(d[0]), "+f"(d[1]), "+f"(d[2]), "+f"(d[3])
        : "r"(a[0]), "r"(a[1]), "r"(a[2]), "r"(a[3]), "r"(b0), "r"(b1));
}
__device__ __forceinline__ void split2(float v, __nv_bfloat16& h, __nv_bfloat16& l) {
    h = __float2bfloat16(v);
    l = __float2bfloat16(v - __bfloat162float(h));
}

// ============================ scratch ========================================
__device__ __align__(1024) float g_xyz [16*2048*3];
__device__ __align__(1024) float g_xyz1[16*512*3];
__device__ __align__(1024) float g_xyz2[16*256*3];
__device__ __align__(1024) float g_f0  [16*2048*64];
__device__ __align__(1024) float g_f1r [16*2048*64];
__device__ __align__(1024) float g_feat1[16*512*128];
__device__ int   g_fps1[16*512];
__device__ int   g_fps2[16*256];
__device__ int   g_knn1[16*512*32];
__device__ int   g_knn2[16*256*32];
__device__ float g_sum[512];
__device__ float g_sq [512];
__device__ float g_ab [1024];
__device__ __align__(1024) float g_bufA[67108864];            // 256 MiB
__device__ __align__(1024) float g_bufB[67108864];            // 256 MiB
__device__ __align__(1024) __nv_bfloat16 g_wbuf[512*1024];    // 1 MiB
__device__ __align__(1024) __nv_bfloat16 g_ctrA[1048576];     // 2 MiB
__device__ __align__(1024) float g_ctrY[2097152];             // 8 MiB

// ============================ small kernels ==================================
__global__ void zero_kernel(float* s, float* q, int C) {
    int c = threadIdx.x;
    if (c < C) { s[c] = 0.f; q[c] = 0.f; }
}

// reads stats, emits (a,b), then ZEROES the stats buffers for the next user
__global__ void bn_finalize(float* __restrict__ sum, float* __restrict__ sq,
                            const float* __restrict__ gamma, const float* __restrict__ beta,
                            float inv_count, int C, float* __restrict__ ab)
{
    int c = threadIdx.x;
    if (c < C) {
        float m = sum[c] * inv_count;
        float v = sq[c] * inv_count - m * m;
        v = fmaxf(v, 0.f);
        float a = gamma[c] * rsqrtf(v + EPSV);
        ab[c] = a;
        ab[C + c] = beta[c] - m * a;
    }
    if (c < 512) { sum[c] = 0.f; sq[c] = 0.f; }
}

__global__ void emb1_kernel(const float* __restrict__ x, const float* __restrict__ w,
                            float* __restrict__ xyz, float* __restrict__ f0,
                            float* __restrict__ sum, float* __restrict__ sq)
{
    __shared__ float ws[192];
    __shared__ float csum[64], csq[64];
    int tid = threadIdx.x;
    if (tid < 192) ws[tid] = w[tid];
    if (tid < 64) { csum[tid] = 0.f; csq[tid] = 0.f; }
    __syncthreads();
    int p = blockIdx.x * 256 + tid;
    int b = p >> 11, n = p & 2047;
    float X = x[(b*3+0)*2048 + n];
    float Y = x[(b*3+1)*2048 + n];
    float Z = x[(b*3+2)*2048 + n];
    xyz[p*3+0] = X; xyz[p*3+1] = Y; xyz[p*3+2] = Z;
    int lane = tid & 31;
    for (int o = 0; o < 64; o++) {
        float y = X*ws[o*3] + Y*ws[o*3+1] + Z*ws[o*3+2];
        f0[(size_t)p*64 + o] = y;
        float t = y, t2 = y*y;
        #pragma unroll
        for (int off = 16; off > 0; off >>= 1) {
            t  += __shfl_xor_sync(0xffffffffu, t,  off);
            t2 += __shfl_xor_sync(0xffffffffu, t2, off);
        }
        if (lane == 0) { atomicAdd(&csum[o], t); atomicAdd(&csq[o], t2); }
    }
    __syncthreads();
    if (tid < 64) { atomicAdd(&sum[tid], csum[tid]); atomicAdd(&sq[tid], csq[tid]); }
}

// fp32 SIMT GEMM (only used for the tiny emb2 GEMM)
template<int BM, int BN, int BK, int TM, int TN>
__global__ void __launch_bounds__(256, 2) gemm_bn_kernel(
    const float* __restrict__ A, const float* __restrict__ W,
    const float* __restrict__ bias, const float* __restrict__ bnA,
    float* __restrict__ C, int M, int N, int K,
    float* __restrict__ sum, float* __restrict__ sq)
{
    constexpr int NTX = BN / TN;
    __shared__ __align__(16) float As[BK][BM + 4];
    __shared__ __align__(16) float Ws[BK][BN + 4];
    __shared__ float csum[BN], csq[BN];
    int tid = threadIdx.x;
    int tx = tid % NTX, ty = tid / NTX;
    int m0 = blockIdx.x * BM, n0 = blockIdx.y * BN;
    if (tid < BN) { csum[tid] = 0.f; csq[tid] = 0.f; }

    float acc[TM][TN];
    #pragma unroll
    for (int i = 0; i < TM; i++)
        #pragma unroll
        for (int j = 0; j < TN; j++) acc[i][j] = 0.f;

    const int lrow = tid / (BK/4);
    const int lcol = (tid % (BK/4)) * 4;
    constexpr int ROWSTEP = 256 / (BK/4);

    for (int k0 = 0; k0 < K; k0 += BK) {
        #pragma unroll
        for (int r = 0; r < BM; r += ROWSTEP) {
            float4 v = *reinterpret_cast<const float4*>(&A[(size_t)(m0 + r + lrow)*K + k0 + lcol]);
            if (bnA) {
                v.x = fmaxf(bnA[k0+lcol+0]*v.x + bnA[K + k0+lcol+0], 0.f);
                v.y = fmaxf(bnA[k0+lcol+1]*v.y + bnA[K + k0+lcol+1], 0.f);
                v.z = fmaxf(bnA[k0+lcol+2]*v.z + bnA[K + k0+lcol+2], 0.f);
                v.w = fmaxf(bnA[k0+lcol+3]*v.w + bnA[K + k0+lcol+3], 0.f);
            }
            As[lcol+0][r+lrow] = v.x; As[lcol+1][r+lrow] = v.y;
            As[lcol+2][r+lrow] = v.z; As[lcol+3][r+lrow] = v.w;
        }
        #pragma unroll
        for (int r = 0; r < BN; r += ROWSTEP) {
            float4 v = *reinterpret_cast<const float4*>(&W[(size_t)(n0 + r + lrow)*K + k0 + lcol]);
            Ws[lcol+0][r+lrow] = v.x; Ws[lcol+1][r+lrow] = v.y;
            Ws[lcol+2][r+lrow] = v.z; Ws[lcol+3][r+lrow] = v.w;
        }
        __syncthreads();
        #pragma unroll
        for (int kk = 0; kk < BK; kk++) {
            float af[TM], wf[TN];
            #pragma unroll
            for (int i = 0; i < TM; i += 4) {
                float4 t = *reinterpret_cast<const float4*>(&As[kk][ty*TM + i]);
                af[i] = t.x; af[i+1] = t.y; af[i+2] = t.z; af[i+3] = t.w;
            }
            #pragma unroll
            for (int j = 0; j < TN; j += 4) {
                float4 t = *reinterpret_cast<const float4*>(&Ws[kk][tx*TN + j]);
                wf[j] = t.x; wf[j+1] = t.y; wf[j+2] = t.z; wf[j+3] = t.w;
            }
            #pragma unroll
            for (int i = 0; i < TM; i++)
                #pragma unroll
                for (int j = 0; j < TN; j++)
                    acc[i][j] = fmaf(af[i], wf[j], acc[i][j]);
        }
        __syncthreads();
    }
    #pragma unroll
    for (int j = 0; j < TN; j++) {
        int n = n0 + tx*TN + j;
        float bsv = bias ? bias[n] : 0.f;
        float s_ = 0.f, q_ = 0.f;
        #pragma unroll
        for (int i = 0; i < TM; i++) {
            float y = acc[i][j] + bsv;
            acc[i][j] = y;
            s_ += y; q_ += y*y;
        }
        atomicAdd(&csum[tx*TN + j], s_);
        atomicAdd(&csq [tx*TN + j], q_);
    }
    #pragma unroll
    for (int i = 0; i < TM; i++) {
        #pragma unroll
        for (int j = 0; j < TN; j += 4) {
            float4 v = make_float4(acc[i][j], acc[i][j+1], acc[i][j+2], acc[i][j+3]);
            *reinterpret_cast<float4*>(&C[(size_t)(m0 + ty*TM + i)*N + n0 + tx*TN + j]) = v;
        }
    }
    __syncthreads();
    if (tid < BN) {
        atomicAdd(&sum[n0 + tid], csum[tid]);
        atomicAdd(&sq [n0 + tid], csq[tid]);
    }
}

// ============ HMMA bf16 split-precision GEMM, 1-sync pipelined ===============
// A: [M, 2K] bf16 = [hi|lo]; W: [N, 2K] bf16 = [hi|lo]
// acc = Ahi·Whi + Alo·Whi + Ahi·Wlo (+bias)(+rowAdd[row>>5]).
// Output: if Cf != nullptr -> fp32 C; else bf16 pair (Chi, Clo).
__device__ __forceinline__ void gemm_issue_chunk(
    const __nv_bfloat16* __restrict__ A, const __nv_bfloat16* __restrict__ W,
    size_t m0, int n0, int K, int K2, uint32_t u0, int tid, int ch, int nch)
{
    if (ch < nch) {
        uint32_t sb = u0 + (uint32_t)(ch % 3) * 32768u;
        int k0 = ch * 32;
        #pragma unroll
        for (int i = 0; i < 8; i++) {
            int idx = i * 256 + tid;          // 0..2047
            int buf = idx >> 9;               // 0:Ahi 1:Alo 2:Whi 3:Wlo
            int r = (idx >> 2) & 127;
            int c16 = idx & 3;
            uint32_t dst = sb + (uint32_t)buf * 8192u
                         + (((uint32_t)(r * 64 + c16 * 16)) ^ (((uint32_t)(r & 6)) << 3));
            const __nv_bfloat16* src;
            if (buf == 0)      src = A + (m0 + r) * K2 + k0 + c16 * 8;
            else if (buf == 1) src = A + (m0 + r) * K2 + K + k0 + c16 * 8;
            else if (buf == 2) src = W + ((size_t)(n0 + r)) * K2 + k0 + c16 * 8;
            else               src = W + ((size_t)(n0 + r)) * K2 + K + k0 + c16 * 8;
            asm volatile("cp.async.cg.shared.global [%0], [%1], 16;" :: "r"(dst), "l"(src));
        }
    }
    asm volatile("cp.async.commit_group;" ::: "memory");
}

extern __shared__ unsigned char dynsm[];

__global__ void __launch_bounds__(256, 2) mma_gemm_kernel(
    const __nv_bfloat16* __restrict__ A, const __nv_bfloat16* __restrict__ W,
    const float* __restrict__ bias,
    float* __restrict__ Cf,
    __nv_bfloat16* __restrict__ Chi, __nv_bfloat16* __restrict__ Clo,
    int N, int K, float* __restrict__ gsum, float* __restrict__ gsq,
    const float* __restrict__ rowAdd)
{
    float* sbias = (float*)(dynsm + 98304);
    float* csum  = sbias + 128;
    float* csq   = csum + 128;

    int tid = threadIdx.x, wid = tid >> 5, lane = tid & 31;
    int n0 = blockIdx.x * 128;
    size_t m0 = (size_t)blockIdx.y * 128;
    int K2 = 2 * K;
    if (tid < 128) {
        sbias[tid] = bias ? bias[n0 + tid] : 0.f;
        csum[tid] = 0.f; csq[tid] = 0.f;
    }

    int wm = (wid & 1) * 64;
    int wn = (wid >> 1) * 32;

    float acc[4][4][4];
    #pragma unroll
    for (int mi = 0; mi < 4; mi++)
        #pragma unroll
        for (int ni = 0; ni < 4; ni++)
            #pragma unroll
            for (int j = 0; j < 4; j++) acc[mi][ni][j] = 0.f;

    uint32_t u0 = smem_to_u32(dynsm);
    int g = lane >> 3, lr = lane & 7;
    uint32_t sw = ((uint32_t)(lr & 6)) << 3;
    uint32_t arow = (uint32_t)((wm + (g & 1) * 8 + lr) * 64);
    uint32_t acol = (uint32_t)((g >> 1) * 16);
    uint32_t brow = (uint32_t)((wn + (g >> 1) * 8 + lr) * 64);
    uint32_t bcol = (uint32_t)((g & 1) * 16);

    const int nch = K >> 5;
    gemm_issue_chunk(A, W, m0, n0, K, K2, u0, tid, 0, nch);
    gemm_issue_chunk(A, W, m0, n0, K, K2, u0, tid, 1, nch);

    for (int ch = 0; ch < nch; ch++) {
        asm volatile("cp.async.wait_group 1;" ::: "memory");
        __syncthreads();
        gemm_issue_chunk(A, W, m0, n0, K, K2, u0, tid, ch + 2, nch);
        uint32_t sb = u0 + (uint32_t)(ch % 3) * 32768u;
        #pragma unroll
        for (int kk = 0; kk < 2; kk++) {
            uint32_t kb = (uint32_t)(kk * 32);
            uint32_t af_hi[4][4], bf_hi[2][4];
            #pragma unroll
            for (int mi = 0; mi < 4; mi++)
                ldsm4(af_hi[mi], sb + arow + (uint32_t)(mi * 1024) + ((kb + acol) ^ sw));
            #pragma unroll
            for (int bi = 0; bi < 2; bi++)
                ldsm4(bf_hi[bi], sb + 16384u + brow + (uint32_t)(bi * 1024) + ((kb + bcol) ^ sw));
            #pragma unroll
            for (int mi = 0; mi < 4; mi++)
                #pragma unroll
                for (int ni = 0; ni < 4; ni++)
                    mma_bf16(acc[mi][ni], af_hi[mi],
                             bf_hi[ni >> 1][(ni & 1) * 2], bf_hi[ni >> 1][(ni & 1) * 2 + 1]);
            {
                uint32_t bf_lo[2][4];
                #pragma unroll
                for (int bi = 0; bi < 2; bi++)
                    ldsm4(bf_lo[bi], sb + 24576u + brow + (uint32_t)(bi * 1024) + ((kb + bcol) ^ sw));
                #pragma unroll
                for (int mi = 0; mi < 4; mi++)
                    #pragma unroll
                    for (int ni = 0; ni < 4; ni++)
                        mma_bf16(acc[mi][ni], af_hi[mi],
                                 bf_lo[ni >> 1][(ni & 1) * 2], bf_lo[ni >> 1][(ni & 1) * 2 + 1]);
            }
            {
                uint32_t af_lo[4][4];
                #pragma unroll
                for (int mi = 0; mi < 4; mi++)
                    ldsm4(af_lo[mi], sb + 8192u + arow + (uint32_t)(mi * 1024) + ((kb + acol) ^ sw));
                #pragma unroll
                for (int mi = 0; mi < 4; mi++)
                    #pragma unroll
                    for (int ni = 0; ni < 4; ni++)
                        mma_bf16(acc[mi][ni], af_lo[mi],
                                 bf_hi[ni >> 1][(ni & 1) * 2], bf_hi[ni >> 1][(ni & 1) * 2 + 1]);
            }
        }
    }
    __syncthreads();

    // epilogue: bias, rowAdd, stats, store (fp32 or bf16 pair)
    int r = lane >> 2, c2 = (lane & 3) << 1;
    float cs[8], cq[8];
    #pragma unroll
    for (int s = 0; s < 8; s++) { cs[s] = 0.f; cq[s] = 0.f; }
    #pragma unroll
    for (int mi = 0; mi < 4; mi++) {
        #pragma unroll
        for (int ni = 0; ni < 4; ni++) {
            int col = wn + ni * 8 + c2;
            float b0v = sbias[col], b1v = sbias[col + 1];
            size_t row = m0 + wm + mi * 16 + r;
            float a00 = 0.f, a01 = 0.f, a10 = 0.f, a11 = 0.f;
            if (rowAdd) {
                const float* r0p = rowAdd + (row >> 5) * (size_t)N + n0 + col;
                const float* r1p = rowAdd + ((row + 8) >> 5) * (size_t)N + n0 + col;
                a00 = r0p[0]; a01 = r0p[1];
                a10 = r1p[0]; a11 = r1p[1];
            }
            float v00 = acc[mi][ni][0] + b0v + a00, v01 = acc[mi][ni][1] + b1v + a01;
            float v10 = acc[mi][ni][2] + b0v + a10, v11 = acc[mi][ni][3] + b1v + a11;
            if (Cf) {
                *reinterpret_cast<float2*>(&Cf[row * (size_t)N + n0 + col]) = make_float2(v00, v01);
                *reinterpret_cast<float2*>(&Cf[(row + 8) * (size_t)N + n0 + col]) = make_float2(v10, v11);
            } else {
                __nv_bfloat16 h0, l0, h1, l1;
                split2(v00, h0, l0); split2(v01, h1, l1);
                __nv_bfloat162 hh; hh.x = h0; hh.y = h1;
                __nv_bfloat162 ll; ll.x = l0; ll.y = l1;
                *reinterpret_cast<__nv_bfloat162*>(&Chi[row * (size_t)N + n0 + col]) = hh;
                *reinterpret_cast<__nv_bfloat162*>(&Clo[row * (size_t)N + n0 + col]) = ll;
                split2(v10, h0, l0); split2(v11, h1, l1);
                hh.x = h0; hh.y = h1; ll.x = l0; ll.y = l1;
                *reinterpret_cast<__nv_bfloat162*>(&Chi[(row + 8) * (size_t)N + n0 + col]) = hh;
                *reinterpret_cast<__nv_bfloat162*>(&Clo[(row + 8) * (size_t)N + n0 + col]) = ll;
            }
            cs[ni*2]   += v00 + v10;  cs[ni*2+1] += v01 + v11;
            cq[ni*2]   += v00*v00 + v10*v10;
            cq[ni*2+1] += v01*v01 + v11*v11;
        }
    }
    if (gsum) {
        #pragma unroll
        for (int s = 0; s < 8; s++) {
            float v = cs[s], q = cq[s];
            #pragma unroll
            for (int o = 4; o <= 16; o <<= 1) {
                v += __shfl_xor_sync(0xffffffffu, v, o);
                q += __shfl_xor_sync(0xffffffffu, q, o);
            }
            if (lane < 4) {
                int col = wn + (s >> 1) * 8 + lane * 2 + (s & 1);
                atomicAdd(&csum[col], v);
                atomicAdd(&csq[col], q);
            }
        }
        __syncthreads();
        if (tid < 128) {
            atomicAdd(&gsum[n0 + tid], csum[tid]);
            atomicAdd(&gsq [n0 + tid], csq[tid]);
        }
    }
}

// ---------------- FPS (1024 threads, ONE barrier per iteration) --------------
__global__ void __launch_bounds__(1024) fps_kernel(
    const float* __restrict__ xyz, int N, int S,
    int* __restrict__ idx_out, float* __restrict__ xyz_out)
{
    __shared__ float px[2048], py[2048], pz[2048], dist[2048];
    __shared__ float rv[2][32];
    __shared__ int   ri[2][32];
    __shared__ int   sidx[512];
    int b = blockIdx.x, tid = threadIdx.x, lane = tid & 31, wid = tid >> 5;
    for (int i = tid; i < N; i += 1024) {
        px[i] = xyz[(b*N + i)*3 + 0];
        py[i] = xyz[(b*N + i)*3 + 1];
        pz[i] = xyz[(b*N + i)*3 + 2];
        dist[i] = 1e10f;
    }
    __syncthreads();
    int sel = 0;
    for (int it = 0; it < S; it++) {
        if (tid == 0) sidx[it] = sel;
        int p = it & 1;
        float sx = px[sel], sy = py[sel], sz = pz[sel];
        float bv = -1.f; int bi = 0x7fffffff;
        for (int j = tid; j < N; j += 1024) {
            float dx = px[j]-sx, dy = py[j]-sy, dz = pz[j]-sz;
            float d = dx*dx + dy*dy + dz*dz;
            float nd = fminf(dist[j], d);
            dist[j] = nd;
            if (nd > bv) { bv = nd; bi = j; }
        }
        #pragma unroll
        for (int o = 16; o > 0; o >>= 1) {
            float ov = __shfl_xor_sync(0xffffffffu, bv, o);
            int   oi = __shfl_xor_sync(0xffffffffu, bi, o);
            if (ov > bv || (ov == bv && oi < bi)) { bv = ov; bi = oi; }
        }
        if (lane == 0) { rv[p][wid] = bv; ri[p][wid] = bi; }
        __syncthreads();
        // every warp redundantly reduces the 32 per-warp winners
        float v = rv[p][lane];
        int  ii = ri[p][lane];
        #pragma unroll
        for (int o = 16; o > 0; o >>= 1) {
            float ov = __shfl_xor_sync(0xffffffffu, v, o);
            int   oi = __shfl_xor_sync(0xffffffffu, ii, o);
            if (ov > v || (ov == v && oi < ii)) { v = ov; ii = oi; }
        }
        sel = ii;
    }
    __syncthreads();
    for (int s = tid; s < S; s += 1024) {
        int i = sidx[s];
        idx_out[b*S + s] = i;
        xyz_out[(b*S + s)*3 + 0] = px[i];
        xyz_out[(b*S + s)*3 + 1] = py[i];
        xyz_out[(b*S + s)*3 + 2] = pz[i];
    }
}

// ---------------- kNN (k=32) -------------------------------------------------
__global__ void knn_kernel(const float* __restrict__ q_xyz, const float* __restrict__ c_xyz,
                           int S, int N, int* __restrict__ knn)
{
    __shared__ float cx[2048], cy[2048], cz[2048];
    int b = blockIdx.y, tid = threadIdx.x;
    for (int i = tid; i < N; i += blockDim.x) {
        cx[i] = c_xyz[(b*N + i)*3 + 0];
        cy[i] = c_xyz[(b*N + i)*3 + 1];
        cz[i] = c_xyz[(b*N + i)*3 + 2];
    }
    __syncthreads();
    int warp = tid >> 5, lane = tid & 31;
    int q = blockIdx.x * (blockDim.x >> 5) + warp;
    if (q >= S) return;
    float qx = q_xyz[(b*S+q)*3+0], qy = q_xyz[(b*S+q)*3+1], qz = q_xyz[(b*S+q)*3+2];
    float topd = 3.4e38f; int topi = 0;
    float curmax = 3.4e38f;
    for (int c0 = 0; c0 < N; c0 += 32) {
        int c = c0 + lane;
        float dx = cx[c]-qx, dy = cy[c]-qy, dz = cz[c]-qz;
        float d = dx*dx + dy*dy + dz*dz;
        unsigned bal = __ballot_sync(0xffffffffu, d < curmax);
        while (bal) {
            int src = __ffs(bal) - 1; bal &= bal - 1;
            float dv = __shfl_sync(0xffffffffu, d, src);
            float mv = topd; int ml = lane;
            #pragma unroll
            for (int off = 16; off > 0; off >>= 1) {
                float ov = __shfl_xor_sync(0xffffffffu, mv, off);
                int   ol = __shfl_xor_sync(0xffffffffu, ml, off);
                if (ov > mv || (ov == mv && ol < ml)) { mv = ov; ml = ol; }
            }
            if (dv < mv && lane == ml) { topd = dv; topi = c0 + src; }
            curmax = mv;
        }
    }
    knn[(b*S + q)*32 + lane] = topi;
}

// ---------------- gathers (rel-only rows + separate ctr buffer) --------------
// stage1: relA rows [hi(64)|lo(64)]; ctrA rows [hi(64)|lo(64)] per query
__global__ void gather1_kernel(const float* __restrict__ f1raw, const int* __restrict__ fps,
                               const int* __restrict__ knn, const float* __restrict__ ab,
                               __nv_bfloat16* __restrict__ relA, __nv_bfloat16* __restrict__ ctrA)
{
    int bs = blockIdx.x;           // b*512+s
    int b = bs >> 9;
    __shared__ float ctr[64];
    int tid = threadIdx.x;
    if (tid < 64) {
        int ci = fps[bs];
        float v = f1raw[(size_t)(b*2048 + ci)*64 + tid];
        v = fmaxf(ab[tid]*v + ab[64+tid], 0.f);
        ctr[tid] = v;
        __nv_bfloat16 h, l; split2(v, h, l);
        ctrA[(size_t)bs*128 + tid] = h;
        ctrA[(size_t)bs*128 + 64 + tid] = l;
    }
    __syncthreads();
    for (int e = tid; e < 32*64; e += 256) {
        int k = e >> 6, c = e & 63;
        int ni = knn[bs*32 + k];
        float v = f1raw[(size_t)(b*2048 + ni)*64 + c];
        v = fmaxf(ab[c]*v + ab[64+c], 0.f) - ctr[c];
        __nv_bfloat16 h, l; split2(v, h, l);
        __nv_bfloat16* p = relA + ((size_t)bs*32 + k) * 128;
        p[c] = h;
        p[64 + c] = l;
    }
}

// stage2: relA rows [hi(128)|lo(128)]; ctrA rows [hi(128)|lo(128)]
__global__ void gather2_kernel(const float* __restrict__ feat, const int* __restrict__ fps,
                               const int* __restrict__ knn,
                               __nv_bfloat16* __restrict__ relA, __nv_bfloat16* __restrict__ ctrA)
{
    int bs = blockIdx.x;           // b*256+s
    int b = bs >> 8;
    __shared__ float ctr[128];
    int tid = threadIdx.x;
    if (tid < 128) {
        int ci = fps[bs];
        float v = feat[(size_t)(b*512 + ci)*128 + tid];
        ctr[tid] = v;
        __nv_bfloat16 h, l; split2(v, h, l);
        ctrA[(size_t)bs*256 + tid] = h;
        ctrA[(size_t)bs*256 + 128 + tid] = l;
    }
    __syncthreads();
    for (int e = tid; e < 32*128; e += 256) {
        int k = e >> 7, c = e & 127;
        int ni = knn[bs*32 + k];
        float v = feat[(size_t)(b*512 + ni)*128 + c] - ctr[c];
        __nv_bfloat16 h, l; split2(v, h, l);
        __nv_bfloat16* p = relA + ((size_t)bs*32 + k) * 256;
        p[c] = h;
        p[128 + c] = l;
    }
}

// BN+ReLU + re-split of a bf16-pair GEMM output: (Xhi,Xlo)[M,C] -> O[M,2C]
__global__ void split_bn_kernel(const __nv_bfloat16* __restrict__ Xhi,
                                const __nv_bfloat16* __restrict__ Xlo,
                                const float* __restrict__ ab,
                                __nv_bfloat16* __restrict__ O, int C, int total_half)
{
    int i = blockIdx.x * 256 + threadIdx.x;
    if (i >= total_half) return;
    int hc = C >> 1;
    int row = i / hc;
    int c = (i - row * hc) * 2;
    __nv_bfloat162 vh = *reinterpret_cast<const __nv_bfloat162*>(&Xhi[(size_t)row * C + c]);
    __nv_bfloat162 vl = *reinterpret_cast<const __nv_bfloat162*>(&Xlo[(size_t)row * C + c]);
    float x0 = __bfloat162float(vh.x) + __bfloat162float(vl.x);
    float x1 = __bfloat162float(vh.y) + __bfloat162float(vl.y);
    float y0 = fmaxf(ab[c]   * x0 + ab[C + c],     0.f);
    float y1 = fmaxf(ab[c+1] * x1 + ab[C + c + 1], 0.f);
    __nv_bfloat16 h0, l0, h1, l1;
    split2(y0, h0, l0); split2(y1, h1, l1);
    __nv_bfloat162 hh; hh.x = h0; hh.y = h1;
    __nv_bfloat162 ll; ll.x = l0; ll.y = l1;
    *reinterpret_cast<__nv_bfloat162*>(&O[(size_t)row * 2 * C + c]) = hh;
    *reinterpret_cast<__nv_bfloat162*>(&O[(size_t)row * 2 * C + C + c]) = ll;
}

// weight split fp32 [N,K] -> bf16 [N,2K] = [hi|lo]
__global__ void wsplit_kernel(const float* __restrict__ W, __nv_bfloat16* __restrict__ O,
                              int K, int total)
{
    int i = blockIdx.x * 256 + threadIdx.x;
    if (i >= total) return;
    int row = i / K, c = i - row * K;
    __nv_bfloat16 h, l; split2(W[i], h, l);
    O[(size_t)row * 2 * K + c] = h;
    O[(size_t)row * 2 * K + K + c] = l;
}

// weight pair split: W [N, K] with K = 2*Khalf = [rel|ctr] columns
__global__ void wsplit_pair_kernel(const float* __restrict__ W,
                                   __nv_bfloat16* __restrict__ Wr,
                                   __nv_bfloat16* __restrict__ Wc,
                                   int K, int Khalf, int total)
{
    int i = blockIdx.x * 256 + threadIdx.x;
    if (i >= total) return;
    int row = i / K, c = i - row * K;
    __nv_bfloat16 h, l; split2(W[i], h, l);
    if (c < Khalf) {
        Wr[(size_t)row * 2 * Khalf + c] = h;
        Wr[(size_t)row * 2 * Khalf + Khalf + c] = l;
    } else {
        int cc = c - Khalf;
        Wc[(size_t)row * 2 * Khalf + cc] = h;
        Wc[(size_t)row * 2 * Khalf + Khalf + cc] = l;
    }
}

// fused BN+relu+max over k, bf16-pair input
__global__ void maxk_kernel(const __nv_bfloat16* __restrict__ hi,
                            const __nv_bfloat16* __restrict__ lo,
                            const float* __restrict__ ab,
                            float* __restrict__ out, int C)
{
    int idx = blockIdx.x * blockDim.x + threadIdx.x;
    int q = idx / C, o = idx - q*C;
    float mx = -3.4e38f, mn = 3.4e38f;
    for (int k = 0; k < 32; k++) {
        size_t off = (size_t)(q*32 + k)*C + o;
        float v = __bfloat162float(hi[off]) + __bfloat162float(lo[off]);
        mx = fmaxf(mx, v); mn = fminf(mn, v);
    }
    float a = ab[o];
    float e = (a >= 0.f) ? mx : mn;
    out[idx] = fmaxf(a*e + ab[C+o], 0.f);
}

__global__ void final_max_kernel(const __nv_bfloat16* __restrict__ hi,
                                 const __nv_bfloat16* __restrict__ lo,
                                 const float* __restrict__ ab,
                                 float* __restrict__ out)
{
    int idx = blockIdx.x * blockDim.x + threadIdx.x;  // 16*256*512
    int o = idx & 511; int q = idx >> 9; int b = q >> 8, s = q & 255;
    float mx = -3.4e38f, mn = 3.4e38f;
    for (int k = 0; k < 32; k++) {
        size_t off = (size_t)(q*32 + k)*512 + o;
        float v = __bfloat162float(hi[off]) + __bfloat162float(lo[off]);
        mx = fmaxf(mx, v); mn = fminf(mn, v);
    }
    float a = ab[o];
    float e = (a >= 0.f) ? mx : mn;
    out[(size_t)(b*512 + o)*256 + s] = fmaxf(a*e + ab[512+o], 0.f);
}

// ============================ driver =========================================
extern "C" void kernel_launch(void* const* d_in, const int* in_sizes, int n_in,
                              void* d_out, int out_size)
{
    const float* x       = (const float*)d_in[0];
    const float* emb_w1  = (const float*)d_in[1];
    const float* emb_g1  = (const float*)d_in[2];
    const float* emb_b1  = (const float*)d_in[3];
    const float* emb_w2  = (const float*)d_in[4];
    const float* emb_g2  = (const float*)d_in[5];
    const float* emb_b2  = (const float*)d_in[6];
    const float* sg1_w1  = (const float*)d_in[7];
    const float* sg1_cb1 = (const float*)d_in[8];
    const float* sg1_g1  = (const float*)d_in[9];
    const float* sg1_b1  = (const float*)d_in[10];
    const float* sg1_w2  = (const float*)d_in[11];
    const float* sg1_cb2 = (const float*)d_in[12];
    const float* sg1_g2  = (const float*)d_in[13];
    const float* sg1_b2  = (const float*)d_in[14];
    const float* sg2_w1  = (const float*)d_in[15];
    const float* sg2_cb1 = (const float*)d_in[16];
    const float* sg2_g1  = (const float*)d_in[17];
    const float* sg2_b1  = (const float*)d_in[18];
    const float* sg2_w2  = (const float*)d_in[19];
    const float* sg2_cb2 = (const float*)d_in[20];
    const float* sg2_g2  = (const float*)d_in[21];
    const float* sg2_b2  = (const float*)d_in[22];
    float* out = (float*)d_out;

    float *xyz, *xyz1, *xyz2, *f0, *f1r, *feat1, *sum, *sq, *ab, *bufA, *bufB, *ctrY;
    __nv_bfloat16 *wbuf, *ctrA;
    int *fps1, *fps2, *knn1, *knn2;
    cudaGetSymbolAddress((void**)&xyz,   g_xyz);
    cudaGetSymbolAddress((void**)&xyz1,  g_xyz1);
    cudaGetSymbolAddress((void**)&xyz2,  g_xyz2);
    cudaGetSymbolAddress((void**)&f0,    g_f0);
    cudaGetSymbolAddress((void**)&f1r,   g_f1r);
    cudaGetSymbolAddress((void**)&feat1, g_feat1);
    cudaGetSymbolAddress((void**)&sum,   g_sum);
    cudaGetSymbolAddress((void**)&sq,    g_sq);
    cudaGetSymbolAddress((void**)&ab,    g_ab);
    cudaGetSymbolAddress((void**)&bufA,  g_bufA);
    cudaGetSymbolAddress((void**)&bufB,  g_bufB);
    cudaGetSymbolAddress((void**)&wbuf,  g_wbuf);
    cudaGetSymbolAddress((void**)&ctrA,  g_ctrA);
    cudaGetSymbolAddress((void**)&ctrY,  g_ctrY);
    cudaGetSymbolAddress((void**)&fps1,  g_fps1);
    cudaGetSymbolAddress((void**)&fps2,  g_fps2);
    cudaGetSymbolAddress((void**)&knn1,  g_knn1);
    cudaGetSymbolAddress((void**)&knn2,  g_knn2);

    cudaFuncSetAttribute(mma_gemm_kernel,
                         cudaFuncAttributeMaxDynamicSharedMemorySize, 99840);
    const int DSM = 99840;

    __nv_bfloat16* bA  = (__nv_bfloat16*)bufA;
    __nv_bfloat16* bHi = (__nv_bfloat16*)bufB;
    __nv_bfloat16* wr  = wbuf;
    __nv_bfloat16* wc  = wbuf + 262144;

    // ---- embedding ----
    zero_kernel<<<1, 512>>>(sum, sq, 512);
    emb1_kernel<<<128, 256>>>(x, emb_w1, xyz, f0, sum, sq);
    bn_finalize<<<1, 512>>>(sum, sq, emb_g1, emb_b1, 1.f/32768.f, 64, ab);
    gemm_bn_kernel<128,64,16,8,4><<<dim3(256, 1), 256>>>(f0, emb_w2, nullptr, ab, f1r,
                                                         32768, 64, 64, sum, sq);
    bn_finalize<<<1, 512>>>(sum, sq, emb_g2, emb_b2, 1.f/32768.f, 64, ab);

    // ---- stage 1 ----
    fps_kernel<<<16, 1024>>>(xyz, 2048, 512, fps1, xyz1);
    knn_kernel<<<dim3(64, 16), 256>>>(xyz1, xyz, 512, 2048, knn1);
    gather1_kernel<<<8192, 256>>>(f1r, fps1, knn1, ab, bA, ctrA);
    wsplit_pair_kernel<<<64, 256>>>(sg1_w1, wr, wc, 128, 64, 128*128);
    // ctr GEMM: [8192, 64] x [128, 64] -> ctrY [8192,128] (fp32)
    mma_gemm_kernel<<<dim3(1, 64), 256, DSM>>>(ctrA, wc, nullptr, ctrY, nullptr, nullptr,
                                               128, 64, nullptr, nullptr, nullptr);
    // main GEMM1: bf16-pair out (Chi=bHi, Clo=bHi+33554432)
    mma_gemm_kernel<<<dim3(1, 2048), 256, DSM>>>(bA, wr, sg1_cb1, nullptr,
                                                 bHi, bHi + 33554432,
                                                 128, 64, sum, sq, ctrY);
    bn_finalize<<<1, 512>>>(sum, sq, sg1_g1, sg1_b1, 1.f/262144.f, 128, ab);
    split_bn_kernel<<<65536, 256>>>(bHi, bHi + 33554432, ab, bA, 128, 16777216);
    wsplit_kernel<<<64, 256>>>(sg1_w2, wbuf, 128, 128*128);
    mma_gemm_kernel<<<dim3(1, 2048), 256, DSM>>>(bA, wbuf, sg1_cb2, nullptr,
                                                 bHi, bHi + 33554432,
                                                 128, 128, sum, sq, nullptr);
    bn_finalize<<<1, 512>>>(sum, sq, sg1_g2, sg1_b2, 1.f/262144.f, 128, ab);
    maxk_kernel<<<1048576/256, 256>>>(bHi, bHi + 33554432, ab, feat1, 128);

    // ---- stage 2 ----
    fps_kernel<<<16, 1024>>>(xyz1, 512, 256, fps2, xyz2);
    knn_kernel<<<dim3(32, 16), 256>>>(xyz2, xyz1, 256, 512, knn2);
    gather2_kernel<<<4096, 256>>>(feat1, fps2, knn2, bA, ctrA);
    wsplit_pair_kernel<<<512, 256>>>(sg2_w1, wr, wc, 256, 128, 512*256);
    // ctr GEMM: [4096, 128] x [512, 128] -> ctrY [4096,512] (fp32)
    mma_gemm_kernel<<<dim3(4, 32), 256, DSM>>>(ctrA, wc, nullptr, ctrY, nullptr, nullptr,
                                               512, 128, nullptr, nullptr, nullptr);
    mma_gemm_kernel<<<dim3(4, 1024), 256, DSM>>>(bA, wr, sg2_cb1, nullptr,
                                                 bHi, bHi + 67108864,
                                                 512, 128, sum, sq, ctrY);
    bn_finalize<<<1, 512>>>(sum, sq, sg2_g1, sg2_b1, 1.f/131072.f, 512, ab);
    split_bn_kernel<<<131072, 256>>>(bHi, bHi + 67108864, ab, bA, 512, 33554432);
    wsplit_kernel<<<1024, 256>>>(sg2_w2, wbuf, 512, 512*512);
    mma_gemm_kernel<<<dim3(4, 1024), 256, DSM>>>(bA, wbuf, sg2_cb2, nullptr,
                                                 bHi, bHi + 67108864,
                                                 512, 512, sum, sq, nullptr);
    bn_finalize<<<1, 512>>>(sum, sq, sg2_g2, sg2_b2, 1.f/131072.f, 512, ab);
    final_max_kernel<<<2097152/256, 256>>>(bHi, bHi + 67108864, ab, out);
}

// round 10
// speedup vs baseline: 1.0817x; 1.0817x over previous
#include <cuda_runtime.h>
#include <cuda_bf16.h>
#include <cstdint>
#include <cstddef>

#define EPSV 1e-5f

__device__ __forceinline__ uint32_t smem_to_u32(const void* p) {
    uint32_t a;
    asm("{ .reg .u64 t; cvta.to.shared.u64 t, %1; cvt.u32.u64 %0, t; }" : "=r"(a) : "l"(p));
    return a;
}
__device__ __forceinline__ void ldsm4(uint32_t* r, uint32_t addr) {
    asm volatile("ldmatrix.sync.aligned.m8n8.x4.shared.b16 {%0,%1,%2,%3}, [%4];"
        : "=r"(r[0]), "=r"(r[1]), "=r"(r[2]), "=r"(r[3]) : "r"(addr));
}
__device__ __forceinline__ void mma_bf16(float* d, const uint32_t* a, uint32_t b0, uint32_t b1) {
    asm volatile("mma.sync.aligned.m16n8k16.row.col.f32.bf16.bf16.f32 "
        "{%0,%1,%2,%3}, {%4,%5,%6,%7}, {%8,%9}, {%0,%1,%2,%3};"
        : "+f"(d[0]), "+f"(d[1]), "+f"(d[2]), "+f"(d[3])
        : "r"(a[0]), "r"(a[1]), "r"(a[2]), "r"(a[3]), "r"(b0), "r"(b1));
}
__device__ __forceinline__ void split2(float v, __nv_bfloat16& h, __nv_bfloat16& l) {
    h = __float2bfloat16(v);
    l = __float2bfloat16(v - __bfloat162float(h));
}

// ============================ scratch ========================================
__device__ __align__(1024) float g_xyz [16*2048*3];
__device__ __align__(1024) float g_xyz1[16*512*3];
__device__ __align__(1024) float g_xyz2[16*256*3];
__device__ __align__(1024) float g_f0  [16*2048*64];
__device__ __align__(1024) float g_f1r [16*2048*64];
__device__ __align__(1024) float g_feat1[16*512*128];
__device__ int   g_fps1[16*512];
__device__ int   g_fps2[16*256];
__device__ int   g_knn1[16*512*32];
__device__ int   g_knn2[16*256*32];
__device__ float g_sum[512];
__device__ float g_sq [512];
__device__ float g_ab [1024];
__device__ __align__(1024) float g_bufA[67108864];            // 256 MiB
__device__ __align__(1024) float g_bufB[67108864];            // 256 MiB
__device__ __align__(1024) __nv_bfloat16 g_wbuf[512*1024];    // 1 MiB
__device__ __align__(1024) __nv_bfloat16 g_ctrA[1048576];     // 2 MiB
__device__ __align__(1024) float g_ctrY[2097152];             // 8 MiB

// ============================ small kernels ==================================
__global__ void zero_kernel(float* s, float* q, int C) {
    int c = threadIdx.x;
    if (c < C) { s[c] = 0.f; q[c] = 0.f; }
}

// reads stats, emits (a,b), then ZEROES the stats buffers for the next user
__global__ void bn_finalize(float* __restrict__ sum, float* __restrict__ sq,
                            const float* __restrict__ gamma, const float* __restrict__ beta,
                            float inv_count, int C, float* __restrict__ ab)
{
    int c = threadIdx.x;
    if (c < C) {
        float m = sum[c] * inv_count;
        float v = sq[c] * inv_count - m * m;
        v = fmaxf(v, 0.f);
        float a = gamma[c] * rsqrtf(v + EPSV);
        ab[c] = a;
        ab[C + c] = beta[c] - m * a;
    }
    if (c < 512) { sum[c] = 0.f; sq[c] = 0.f; }
}

__global__ void emb1_kernel(const float* __restrict__ x, const float* __restrict__ w,
                            float* __restrict__ xyz, float* __restrict__ f0,
                            float* __restrict__ sum, float* __restrict__ sq)
{
    __shared__ float ws[192];
    __shared__ float csum[64], csq[64];
    int tid = threadIdx.x;
    if (tid < 192) ws[tid] = w[tid];
    if (tid < 64) { csum[tid] = 0.f; csq[tid] = 0.f; }
    __syncthreads();
    int p = blockIdx.x * 256 + tid;
    int b = p >> 11, n = p & 2047;
    float X = x[(b*3+0)*2048 + n];
    float Y = x[(b*3+1)*2048 + n];
    float Z = x[(b*3+2)*2048 + n];
    xyz[p*3+0] = X; xyz[p*3+1] = Y; xyz[p*3+2] = Z;
    int lane = tid & 31;
    for (int o = 0; o < 64; o++) {
        float y = X*ws[o*3] + Y*ws[o*3+1] + Z*ws[o*3+2];
        f0[(size_t)p*64 + o] = y;
        float t = y, t2 = y*y;
        #pragma unroll
        for (int off = 16; off > 0; off >>= 1) {
            t  += __shfl_xor_sync(0xffffffffu, t,  off);
            t2 += __shfl_xor_sync(0xffffffffu, t2, off);
        }
        if (lane == 0) { atomicAdd(&csum[o], t); atomicAdd(&csq[o], t2); }
    }
    __syncthreads();
    if (tid < 64) { atomicAdd(&sum[tid], csum[tid]); atomicAdd(&sq[tid], csq[tid]); }
}

// fp32 SIMT GEMM (only used for the tiny emb2 GEMM)
template<int BM, int BN, int BK, int TM, int TN>
__global__ void __launch_bounds__(256, 2) gemm_bn_kernel(
    const float* __restrict__ A, const float* __restrict__ W,
    const float* __restrict__ bias, const float* __restrict__ bnA,
    float* __restrict__ C, int M, int N, int K,
    float* __restrict__ sum, float* __restrict__ sq)
{
    constexpr int NTX = BN / TN;
    __shared__ __align__(16) float As[BK][BM + 4];
    __shared__ __align__(16) float Ws[BK][BN + 4];
    __shared__ float csum[BN], csq[BN];
    int tid = threadIdx.x;
    int tx = tid % NTX, ty = tid / NTX;
    int m0 = blockIdx.x * BM, n0 = blockIdx.y * BN;
    if (tid < BN) { csum[tid] = 0.f; csq[tid] = 0.f; }

    float acc[TM][TN];
    #pragma unroll
    for (int i = 0; i < TM; i++)
        #pragma unroll
        for (int j = 0; j < TN; j++) acc[i][j] = 0.f;

    const int lrow = tid / (BK/4);
    const int lcol = (tid % (BK/4)) * 4;
    constexpr int ROWSTEP = 256 / (BK/4);

    for (int k0 = 0; k0 < K; k0 += BK) {
        #pragma unroll
        for (int r = 0; r < BM; r += ROWSTEP) {
            float4 v = *reinterpret_cast<const float4*>(&A[(size_t)(m0 + r + lrow)*K + k0 + lcol]);
            if (bnA) {
                v.x = fmaxf(bnA[k0+lcol+0]*v.x + bnA[K + k0+lcol+0], 0.f);
                v.y = fmaxf(bnA[k0+lcol+1]*v.y + bnA[K + k0+lcol+1], 0.f);
                v.z = fmaxf(bnA[k0+lcol+2]*v.z + bnA[K + k0+lcol+2], 0.f);
                v.w = fmaxf(bnA[k0+lcol+3]*v.w + bnA[K + k0+lcol+3], 0.f);
            }
            As[lcol+0][r+lrow] = v.x; As[lcol+1][r+lrow] = v.y;
            As[lcol+2][r+lrow] = v.z; As[lcol+3][r+lrow] = v.w;
        }
        #pragma unroll
        for (int r = 0; r < BN; r += ROWSTEP) {
            float4 v = *reinterpret_cast<const float4*>(&W[(size_t)(n0 + r + lrow)*K + k0 + lcol]);
            Ws[lcol+0][r+lrow] = v.x; Ws[lcol+1][r+lrow] = v.y;
            Ws[lcol+2][r+lrow] = v.z; Ws[lcol+3][r+lrow] = v.w;
        }
        __syncthreads();
        #pragma unroll
        for (int kk = 0; kk < BK; kk++) {
            float af[TM], wf[TN];
            #pragma unroll
            for (int i = 0; i < TM; i += 4) {
                float4 t = *reinterpret_cast<const float4*>(&As[kk][ty*TM + i]);
                af[i] = t.x; af[i+1] = t.y; af[i+2] = t.z; af[i+3] = t.w;
            }
            #pragma unroll
            for (int j = 0; j < TN; j += 4) {
                float4 t = *reinterpret_cast<const float4*>(&Ws[kk][tx*TN + j]);
                wf[j] = t.x; wf[j+1] = t.y; wf[j+2] = t.z; wf[j+3] = t.w;
            }
            #pragma unroll
            for (int i = 0; i < TM; i++)
                #pragma unroll
                for (int j = 0; j < TN; j++)
                    acc[i][j] = fmaf(af[i], wf[j], acc[i][j]);
        }
        __syncthreads();
    }
    #pragma unroll
    for (int j = 0; j < TN; j++) {
        int n = n0 + tx*TN + j;
        float bsv = bias ? bias[n] : 0.f;
        float s_ = 0.f, q_ = 0.f;
        #pragma unroll
        for (int i = 0; i < TM; i++) {
            float y = acc[i][j] + bsv;
            acc[i][j] = y;
            s_ += y; q_ += y*y;
        }
        atomicAdd(&csum[tx*TN + j], s_);
        atomicAdd(&csq [tx*TN + j], q_);
    }
    #pragma unroll
    for (int i = 0; i < TM; i++) {
        #pragma unroll
        for (int j = 0; j < TN; j += 4) {
            float4 v = make_float4(acc[i][j], acc[i][j+1], acc[i][j+2], acc[i][j+3]);
            *reinterpret_cast<float4*>(&C[(size_t)(m0 + ty*TM + i)*N + n0 + tx*TN + j]) = v;
        }
    }
    __syncthreads();
    if (tid < BN) {
        atomicAdd(&sum[n0 + tid], csum[tid]);
        atomicAdd(&sq [n0 + tid], csq[tid]);
    }
}

// ============ HMMA bf16 split-precision GEMM, 1-sync pipelined ===============
// A: [M, 2K] bf16 = [hi|lo]; W: [N, 2K] bf16 = [hi|lo]; C = A·Wᵀ (+bias)(+rowAdd)
// acc = Ahi·Whi + Alo·Whi + Ahi·Wlo.  CTA tile 128x128, K-chunk 32.
// rowAdd (optional): fp32 [M>>5, N] added per output row (row>>5 indexing).
// gsum==nullptr skips BN stats.  bias==nullptr -> 0.
__device__ __forceinline__ void gemm_issue_chunk(
    const __nv_bfloat16* __restrict__ A, const __nv_bfloat16* __restrict__ W,
    size_t m0, int n0, int K, int K2, uint32_t u0, int tid, int ch, int nch)
{
    if (ch < nch) {
        uint32_t sb = u0 + (uint32_t)(ch % 3) * 32768u;
        int k0 = ch * 32;
        #pragma unroll
        for (int i = 0; i < 8; i++) {
            int idx = i * 256 + tid;          // 0..2047
            int buf = idx >> 9;               // 0:Ahi 1:Alo 2:Whi 3:Wlo
            int r = (idx >> 2) & 127;
            int c16 = idx & 3;
            uint32_t dst = sb + (uint32_t)buf * 8192u
                         + (((uint32_t)(r * 64 + c16 * 16)) ^ (((uint32_t)(r & 6)) << 3));
            const __nv_bfloat16* src;
            if (buf == 0)      src = A + (m0 + r) * K2 + k0 + c16 * 8;
            else if (buf == 1) src = A + (m0 + r) * K2 + K + k0 + c16 * 8;
            else if (buf == 2) src = W + ((size_t)(n0 + r)) * K2 + k0 + c16 * 8;
            else               src = W + ((size_t)(n0 + r)) * K2 + K + k0 + c16 * 8;
            asm volatile("cp.async.cg.shared.global [%0], [%1], 16;" :: "r"(dst), "l"(src));
        }
    }
    asm volatile("cp.async.commit_group;" ::: "memory");
}

extern __shared__ unsigned char dynsm[];

__global__ void __launch_bounds__(256, 2) mma_gemm_kernel(
    const __nv_bfloat16* __restrict__ A, const __nv_bfloat16* __restrict__ W,
    const float* __restrict__ bias, float* __restrict__ C,
    int N, int K, float* __restrict__ gsum, float* __restrict__ gsq,
    const float* __restrict__ rowAdd)
{
    float* sbias = (float*)(dynsm + 98304);
    float* csum  = sbias + 128;
    float* csq   = csum + 128;

    int tid = threadIdx.x, wid = tid >> 5, lane = tid & 31;
    int n0 = blockIdx.x * 128;
    size_t m0 = (size_t)blockIdx.y * 128;
    int K2 = 2 * K;
    if (tid < 128) {
        sbias[tid] = bias ? bias[n0 + tid] : 0.f;
        csum[tid] = 0.f; csq[tid] = 0.f;
    }

    int wm = (wid & 1) * 64;
    int wn = (wid >> 1) * 32;

    float acc[4][4][4];
    #pragma unroll
    for (int mi = 0; mi < 4; mi++)
        #pragma unroll
        for (int ni = 0; ni < 4; ni++)
            #pragma unroll
            for (int j = 0; j < 4; j++) acc[mi][ni][j] = 0.f;

    uint32_t u0 = smem_to_u32(dynsm);
    int g = lane >> 3, lr = lane & 7;
    uint32_t sw = ((uint32_t)(lr & 6)) << 3;
    uint32_t arow = (uint32_t)((wm + (g & 1) * 8 + lr) * 64);
    uint32_t acol = (uint32_t)((g >> 1) * 16);
    uint32_t brow = (uint32_t)((wn + (g >> 1) * 8 + lr) * 64);
    uint32_t bcol = (uint32_t)((g & 1) * 16);

    const int nch = K >> 5;
    gemm_issue_chunk(A, W, m0, n0, K, K2, u0, tid, 0, nch);
    gemm_issue_chunk(A, W, m0, n0, K, K2, u0, tid, 1, nch);

    for (int ch = 0; ch < nch; ch++) {
        asm volatile("cp.async.wait_group 1;" ::: "memory");
        __syncthreads();
        gemm_issue_chunk(A, W, m0, n0, K, K2, u0, tid, ch + 2, nch);
        uint32_t sb = u0 + (uint32_t)(ch % 3) * 32768u;
        #pragma unroll
        for (int kk = 0; kk < 2; kk++) {
            uint32_t kb = (uint32_t)(kk * 32);
            uint32_t af_hi[4][4], bf_hi[2][4];
            #pragma unroll
            for (int mi = 0; mi < 4; mi++)
                ldsm4(af_hi[mi], sb + arow + (uint32_t)(mi * 1024) + ((kb + acol) ^ sw));
            #pragma unroll
            for (int bi = 0; bi < 2; bi++)
                ldsm4(bf_hi[bi], sb + 16384u + brow + (uint32_t)(bi * 1024) + ((kb + bcol) ^ sw));
            #pragma unroll
            for (int mi = 0; mi < 4; mi++)
                #pragma unroll
                for (int ni = 0; ni < 4; ni++)
                    mma_bf16(acc[mi][ni], af_hi[mi],
                             bf_hi[ni >> 1][(ni & 1) * 2], bf_hi[ni >> 1][(ni & 1) * 2 + 1]);
            {
                uint32_t bf_lo[2][4];
                #pragma unroll
                for (int bi = 0; bi < 2; bi++)
                    ldsm4(bf_lo[bi], sb + 24576u + brow + (uint32_t)(bi * 1024) + ((kb + bcol) ^ sw));
                #pragma unroll
                for (int mi = 0; mi < 4; mi++)
                    #pragma unroll
                    for (int ni = 0; ni < 4; ni++)
                        mma_bf16(acc[mi][ni], af_hi[mi],
                                 bf_lo[ni >> 1][(ni & 1) * 2], bf_lo[ni >> 1][(ni & 1) * 2 + 1]);
            }
            {
                uint32_t af_lo[4][4];
                #pragma unroll
                for (int mi = 0; mi < 4; mi++)
                    ldsm4(af_lo[mi], sb + 8192u + arow + (uint32_t)(mi * 1024) + ((kb + acol) ^ sw));
                #pragma unroll
                for (int mi = 0; mi < 4; mi++)
                    #pragma unroll
                    for (int ni = 0; ni < 4; ni++)
                        mma_bf16(acc[mi][ni], af_lo[mi],
                                 bf_hi[ni >> 1][(ni & 1) * 2], bf_hi[ni >> 1][(ni & 1) * 2 + 1]);
            }
        }
    }
    __syncthreads();

    // epilogue: bias, rowAdd, stats, store
    int r = lane >> 2, c2 = (lane & 3) << 1;
    float cs[8], cq[8];
    #pragma unroll
    for (int s = 0; s < 8; s++) { cs[s] = 0.f; cq[s] = 0.f; }
    #pragma unroll
    for (int mi = 0; mi < 4; mi++) {
        #pragma unroll
        for (int ni = 0; ni < 4; ni++) {
            int col = wn + ni * 8 + c2;
            float b0v = sbias[col], b1v = sbias[col + 1];
            size_t row = m0 + wm + mi * 16 + r;
            float a00 = 0.f, a01 = 0.f, a10 = 0.f, a11 = 0.f;
            if (rowAdd) {
                const float* r0p = rowAdd + (row >> 5) * (size_t)N + n0 + col;
                const float* r1p = rowAdd + ((row + 8) >> 5) * (size_t)N + n0 + col;
                a00 = r0p[0]; a01 = r0p[1];
                a10 = r1p[0]; a11 = r1p[1];
            }
            float v00 = acc[mi][ni][0] + b0v + a00, v01 = acc[mi][ni][1] + b1v + a01;
            float v10 = acc[mi][ni][2] + b0v + a10, v11 = acc[mi][ni][3] + b1v + a11;
            *reinterpret_cast<float2*>(&C[row * (size_t)N + n0 + col]) = make_float2(v00, v01);
            *reinterpret_cast<float2*>(&C[(row + 8) * (size_t)N + n0 + col]) = make_float2(v10, v11);
            cs[ni*2]   += v00 + v10;  cs[ni*2+1] += v01 + v11;
            cq[ni*2]   += v00*v00 + v10*v10;
            cq[ni*2+1] += v01*v01 + v11*v11;
        }
    }
    if (gsum) {
        #pragma unroll
        for (int s = 0; s < 8; s++) {
            float v = cs[s], q = cq[s];
            #pragma unroll
            for (int o = 4; o <= 16; o <<= 1) {
                v += __shfl_xor_sync(0xffffffffu, v, o);
                q += __shfl_xor_sync(0xffffffffu, q, o);
            }
            if (lane < 4) {
                int col = wn + (s >> 1) * 8 + lane * 2 + (s & 1);
                atomicAdd(&csum[col], v);
                atomicAdd(&csq[col], q);
            }
        }
        __syncthreads();
        if (tid < 128) {
            atomicAdd(&gsum[n0 + tid], csum[tid]);
            atomicAdd(&gsq [n0 + tid], csq[tid]);
        }
    }
}

// ---------------- FPS (1024 threads, ONE barrier per iteration) --------------
__global__ void __launch_bounds__(1024) fps_kernel(
    const float* __restrict__ xyz, int N, int S,
    int* __restrict__ idx_out, float* __restrict__ xyz_out)
{
    __shared__ float px[2048], py[2048], pz[2048], dist[2048];
    __shared__ float rv[2][32];
    __shared__ int   ri[2][32];
    __shared__ int   sidx[512];
    int b = blockIdx.x, tid = threadIdx.x, lane = tid & 31, wid = tid >> 5;
    for (int i = tid; i < N; i += 1024) {
        px[i] = xyz[(b*N + i)*3 + 0];
        py[i] = xyz[(b*N + i)*3 + 1];
        pz[i] = xyz[(b*N + i)*3 + 2];
        dist[i] = 1e10f;
    }
    __syncthreads();
    int sel = 0;
    for (int it = 0; it < S; it++) {
        if (tid == 0) sidx[it] = sel;
        int p = it & 1;
        float sx = px[sel], sy = py[sel], sz = pz[sel];
        float bv = -1.f; int bi = 0x7fffffff;
        for (int j = tid; j < N; j += 1024) {
            float dx = px[j]-sx, dy = py[j]-sy, dz = pz[j]-sz;
            float d = dx*dx + dy*dy + dz*dz;
            float nd = fminf(dist[j], d);
            dist[j] = nd;
            if (nd > bv) { bv = nd; bi = j; }
        }
        #pragma unroll
        for (int o = 16; o > 0; o >>= 1) {
            float ov = __shfl_xor_sync(0xffffffffu, bv, o);
            int   oi = __shfl_xor_sync(0xffffffffu, bi, o);
            if (ov > bv || (ov == bv && oi < bi)) { bv = ov; bi = oi; }
        }
        if (lane == 0) { rv[p][wid] = bv; ri[p][wid] = bi; }
        __syncthreads();
        float v = rv[p][lane];
        int  ii = ri[p][lane];
        #pragma unroll
        for (int o = 16; o > 0; o >>= 1) {
            float ov = __shfl_xor_sync(0xffffffffu, v, o);
            int   oi = __shfl_xor_sync(0xffffffffu, ii, o);
            if (ov > v || (ov == v && oi < ii)) { v = ov; ii = oi; }
        }
        sel = ii;
    }
    __syncthreads();
    for (int s = tid; s < S; s += 1024) {
        int i = sidx[s];
        idx_out[b*S + s] = i;
        xyz_out[(b*S + s)*3 + 0] = px[i];
        xyz_out[(b*S + s)*3 + 1] = py[i];
        xyz_out[(b*S + s)*3 + 2] = pz[i];
    }
}

// ---------------- kNN (k=32) -------------------------------------------------
__global__ void knn_kernel(const float* __restrict__ q_xyz, const float* __restrict__ c_xyz,
                           int S, int N, int* __restrict__ knn)
{
    __shared__ float cx[2048], cy[2048], cz[2048];
    int b = blockIdx.y, tid = threadIdx.x;
    for (int i = tid; i < N; i += blockDim.x) {
        cx[i] = c_xyz[(b*N + i)*3 + 0];
        cy[i] = c_xyz[(b*N + i)*3 + 1];
        cz[i] = c_xyz[(b*N + i)*3 + 2];
    }
    __syncthreads();
    int warp = tid >> 5, lane = tid & 31;
    int q = blockIdx.x * (blockDim.x >> 5) + warp;
    if (q >= S) return;
    float qx = q_xyz[(b*S+q)*3+0], qy = q_xyz[(b*S+q)*3+1], qz = q_xyz[(b*S+q)*3+2];
    float topd = 3.4e38f; int topi = 0;
    float curmax = 3.4e38f;
    for (int c0 = 0; c0 < N; c0 += 32) {
        int c = c0 + lane;
        float dx = cx[c]-qx, dy = cy[c]-qy, dz = cz[c]-qz;
        float d = dx*dx + dy*dy + dz*dz;
        unsigned bal = __ballot_sync(0xffffffffu, d < curmax);
        while (bal) {
            int src = __ffs(bal) - 1; bal &= bal - 1;
            float dv = __shfl_sync(0xffffffffu, d, src);
            float mv = topd; int ml = lane;
            #pragma unroll
            for (int off = 16; off > 0; off >>= 1) {
                float ov = __shfl_xor_sync(0xffffffffu, mv, off);
                int   ol = __shfl_xor_sync(0xffffffffu, ml, off);
                if (ov > mv || (ov == mv && ol < ml)) { mv = ov; ml = ol; }
            }
            if (dv < mv && lane == ml) { topd = dv; topi = c0 + src; }
            curmax = mv;
        }
    }
    knn[(b*S + q)*32 + lane] = topi;
}

// ---------------- gathers (rel-only rows + separate ctr buffer) --------------
// stage1: relA rows [hi(64)|lo(64)]; ctrA rows [hi(64)|lo(64)] per query
__global__ void gather1_kernel(const float* __restrict__ f1raw, const int* __restrict__ fps,
                               const int* __restrict__ knn, const float* __restrict__ ab,
                               __nv_bfloat16* __restrict__ relA, __nv_bfloat16* __restrict__ ctrA)
{
    int bs = blockIdx.x;           // b*512+s
    int b = bs >> 9;
    __shared__ float ctr[64];
    int tid = threadIdx.x;
    if (tid < 64) {
        int ci = fps[bs];
        float v = f1raw[(size_t)(b*2048 + ci)*64 + tid];
        v = fmaxf(ab[tid]*v + ab[64+tid], 0.f);
        ctr[tid] = v;
        __nv_bfloat16 h, l; split2(v, h, l);
        ctrA[(size_t)bs*128 + tid] = h;
        ctrA[(size_t)bs*128 + 64 + tid] = l;
    }
    __syncthreads();
    for (int e = tid; e < 32*64; e += 256) {
        int k = e >> 6, c = e & 63;
        int ni = knn[bs*32 + k];
        float v = f1raw[(size_t)(b*2048 + ni)*64 + c];
        v = fmaxf(ab[c]*v + ab[64+c], 0.f) - ctr[c];
        __nv_bfloat16 h, l; split2(v, h, l);
        __nv_bfloat16* p = relA + ((size_t)bs*32 + k) * 128;
        p[c] = h;
        p[64 + c] = l;
    }
}

// stage2: relA rows [hi(128)|lo(128)]; ctrA rows [hi(128)|lo(128)]
__global__ void gather2_kernel(const float* __restrict__ feat, const int* __restrict__ fps,
                               const int* __restrict__ knn,
                               __nv_bfloat16* __restrict__ relA, __nv_bfloat16* __restrict__ ctrA)
{
    int bs = blockIdx.x;           // b*256+s
    int b = bs >> 8;
    __shared__ float ctr[128];
    int tid = threadIdx.x;
    if (tid < 128) {
        int ci = fps[bs];
        float v = feat[(size_t)(b*512 + ci)*128 + tid];
        ctr[tid] = v;
        __nv_bfloat16 h, l; split2(v, h, l);
        ctrA[(size_t)bs*256 + tid] = h;
        ctrA[(size_t)bs*256 + 128 + tid] = l;
    }
    __syncthreads();
    for (int e = tid; e < 32*128; e += 256) {
        int k = e >> 7, c = e & 127;
        int ni = knn[bs*32 + k];
        float v = feat[(size_t)(b*512 + ni)*128 + c] - ctr[c];
        __nv_bfloat16 h, l; split2(v, h, l);
        __nv_bfloat16* p = relA + ((size_t)bs*32 + k) * 256;
        p[c] = h;
        p[128 + c] = l;
    }
}

// BN+ReLU + hi/lo split of a raw GEMM output: X[M,C] -> O[M,2C]
__global__ void split_bn_kernel(const float* __restrict__ X, const float* __restrict__ ab,
                                __nv_bfloat16* __restrict__ O, int C, int total_half)
{
    int i = blockIdx.x * 256 + threadIdx.x;
    if (i >= total_half) return;
    int hc = C >> 1;
    int row = i / hc;
    int c = (i - row * hc) * 2;
    float2 v = *reinterpret_cast<const float2*>(&X[(size_t)row * C + c]);
    float y0 = fmaxf(ab[c]   * v.x + ab[C + c],     0.f);
    float y1 = fmaxf(ab[c+1] * v.y + ab[C + c + 1], 0.f);
    __nv_bfloat16 h0, l0, h1, l1;
    split2(y0, h0, l0); split2(y1, h1, l1);
    __nv_bfloat162 hh; hh.x = h0; hh.y = h1;
    __nv_bfloat162 ll; ll.x = l0; ll.y = l1;
    *reinterpret_cast<__nv_bfloat162*>(&O[(size_t)row * 2 * C + c]) = hh;
    *reinterpret_cast<__nv_bfloat162*>(&O[(size_t)row * 2 * C + C + c]) = ll;
}

// weight split fp32 [N,K] -> bf16 [N,2K] = [hi|lo]
__global__ void wsplit_kernel(const float* __restrict__ W, __nv_bfloat16* __restrict__ O,
                              int K, int total)
{
    int i = blockIdx.x * 256 + threadIdx.x;
    if (i >= total) return;
    int row = i / K, c = i - row * K;
    __nv_bfloat16 h, l; split2(W[i], h, l);
    O[(size_t)row * 2 * K + c] = h;
    O[(size_t)row * 2 * K + K + c] = l;
}

// weight pair split: W [N, K] with K = 2*Khalf = [rel|ctr] columns
__global__ void wsplit_pair_kernel(const float* __restrict__ W,
                                   __nv_bfloat16* __restrict__ Wr,
                                   __nv_bfloat16* __restrict__ Wc,
                                   int K, int Khalf, int total)
{
    int i = blockIdx.x * 256 + threadIdx.x;
    if (i >= total) return;
    int row = i / K, c = i - row * K;
    __nv_bfloat16 h, l; split2(W[i], h, l);
    if (c < Khalf) {
        Wr[(size_t)row * 2 * Khalf + c] = h;
        Wr[(size_t)row * 2 * Khalf + Khalf + c] = l;
    } else {
        int cc = c - Khalf;
        Wc[(size_t)row * 2 * Khalf + cc] = h;
        Wc[(size_t)row * 2 * Khalf + Khalf + cc] = l;
    }
}

// fused BN+relu+max over k
__global__ void maxk_kernel(const float* __restrict__ h, const float* __restrict__ ab,
                            float* __restrict__ out, int C)
{
    int idx = blockIdx.x * blockDim.x + threadIdx.x;
    int q = idx / C, o = idx - q*C;
    float mx = -3.4e38f, mn = 3.4e38f;
    for (int k = 0; k < 32; k++) {
        float v = h[(size_t)(q*32 + k)*C + o];
        mx = fmaxf(mx, v); mn = fminf(mn, v);
    }
    float a = ab[o];
    float e = (a >= 0.f) ? mx : mn;
    out[idx] = fmaxf(a*e + ab[C+o], 0.f);
}

__global__ void final_max_kernel(const float* __restrict__ h, const float* __restrict__ ab,
                                 float* __restrict__ out)
{
    int idx = blockIdx.x * blockDim.x + threadIdx.x;  // 16*256*512
    int o = idx & 511; int q = idx >> 9; int b = q >> 8, s = q & 255;
    float mx = -3.4e38f, mn = 3.4e38f;
    for (int k = 0; k < 32; k++) {
        float v = h[(size_t)(q*32 + k)*512 + o];
        mx = fmaxf(mx, v); mn = fminf(mn, v);
    }
    float a = ab[o];
    float e = (a >= 0.f) ? mx : mn;
    out[(size_t)(b*512 + o)*256 + s] = fmaxf(a*e + ab[512+o], 0.f);
}

// ============================ driver =========================================
extern "C" void kernel_launch(void* const* d_in, const int* in_sizes, int n_in,
                              void* d_out, int out_size)
{
    const float* x       = (const float*)d_in[0];
    const float* emb_w1  = (const float*)d_in[1];
    const float* emb_g1  = (const float*)d_in[2];
    const float* emb_b1  = (const float*)d_in[3];
    const float* emb_w2  = (const float*)d_in[4];
    const float* emb_g2  = (const float*)d_in[5];
    const float* emb_b2  = (const float*)d_in[6];
    const float* sg1_w1  = (const float*)d_in[7];
    const float* sg1_cb1 = (const float*)d_in[8];
    const float* sg1_g1  = (const float*)d_in[9];
    const float* sg1_b1  = (const float*)d_in[10];
    const float* sg1_w2  = (const float*)d_in[11];
    const float* sg1_cb2 = (const float*)d_in[12];
    const float* sg1_g2  = (const float*)d_in[13];
    const float* sg1_b2  = (const float*)d_in[14];
    const float* sg2_w1  = (const float*)d_in[15];
    const float* sg2_cb1 = (const float*)d_in[16];
    const float* sg2_g1  = (const float*)d_in[17];
    const float* sg2_b1  = (const float*)d_in[18];
    const float* sg2_w2  = (const float*)d_in[19];
    const float* sg2_cb2 = (const float*)d_in[20];
    const float* sg2_g2  = (const float*)d_in[21];
    const float* sg2_b2  = (const float*)d_in[22];
    float* out = (float*)d_out;

    float *xyz, *xyz1, *xyz2, *f0, *f1r, *feat1, *sum, *sq, *ab, *bufA, *bufB, *ctrY;
    __nv_bfloat16 *wbuf, *ctrA;
    int *fps1, *fps2, *knn1, *knn2;
    cudaGetSymbolAddress((void**)&xyz,   g_xyz);
    cudaGetSymbolAddress((void**)&xyz1,  g_xyz1);
    cudaGetSymbolAddress((void**)&xyz2,  g_xyz2);
    cudaGetSymbolAddress((void**)&f0,    g_f0);
    cudaGetSymbolAddress((void**)&f1r,   g_f1r);
    cudaGetSymbolAddress((void**)&feat1, g_feat1);
    cudaGetSymbolAddress((void**)&sum,   g_sum);
    cudaGetSymbolAddress((void**)&sq,    g_sq);
    cudaGetSymbolAddress((void**)&ab,    g_ab);
    cudaGetSymbolAddress((void**)&bufA,  g_bufA);
    cudaGetSymbolAddress((void**)&bufB,  g_bufB);
    cudaGetSymbolAddress((void**)&wbuf,  g_wbuf);
    cudaGetSymbolAddress((void**)&ctrA,  g_ctrA);
    cudaGetSymbolAddress((void**)&ctrY,  g_ctrY);
    cudaGetSymbolAddress((void**)&fps1,  g_fps1);
    cudaGetSymbolAddress((void**)&fps2,  g_fps2);
    cudaGetSymbolAddress((void**)&knn1,  g_knn1);
    cudaGetSymbolAddress((void**)&knn2,  g_knn2);

    cudaFuncSetAttribute(mma_gemm_kernel,
                         cudaFuncAttributeMaxDynamicSharedMemorySize, 99840);
    const int DSM = 99840;

    __nv_bfloat16* bA = (__nv_bfloat16*)bufA;
    __nv_bfloat16* wr = wbuf;
    __nv_bfloat16* wc = wbuf + 262144;

    // ---- embedding ----
    zero_kernel<<<1, 512>>>(sum, sq, 512);
    emb1_kernel<<<128, 256>>>(x, emb_w1, xyz, f0, sum, sq);
    bn_finalize<<<1, 512>>>(sum, sq, emb_g1, emb_b1, 1.f/32768.f, 64, ab);
    gemm_bn_kernel<128,64,16,8,4><<<dim3(256, 1), 256>>>(f0, emb_w2, nullptr, ab, f1r,
                                                         32768, 64, 64, sum, sq);
    bn_finalize<<<1, 512>>>(sum, sq, emb_g2, emb_b2, 1.f/32768.f, 64, ab);

    // ---- stage 1 ----
    fps_kernel<<<16, 1024>>>(xyz, 2048, 512, fps1, xyz1);
    knn_kernel<<<dim3(64, 16), 256>>>(xyz1, xyz, 512, 2048, knn1);
    gather1_kernel<<<8192, 256>>>(f1r, fps1, knn1, ab, bA, ctrA);
    wsplit_pair_kernel<<<64, 256>>>(sg1_w1, wr, wc, 128, 64, 128*128);
    // ctr GEMM: [8192, 64] x [128, 64] -> ctrY [8192,128]
    mma_gemm_kernel<<<dim3(1, 64), 256, DSM>>>(ctrA, wc, nullptr, ctrY, 128, 64,
                                               nullptr, nullptr, nullptr);
    // main GEMM: rel [262144, 64] x Wr + bias + ctrY[row>>5]
    mma_gemm_kernel<<<dim3(1, 2048), 256, DSM>>>(bA, wr, sg1_cb1, bufB, 128, 64,
                                                 sum, sq, ctrY);
    bn_finalize<<<1, 512>>>(sum, sq, sg1_g1, sg1_b1, 1.f/262144.f, 128, ab);
    split_bn_kernel<<<65536, 256>>>(bufB, ab, bA, 128, 16777216);
    wsplit_kernel<<<64, 256>>>(sg1_w2, wbuf, 128, 128*128);
    mma_gemm_kernel<<<dim3(1, 2048), 256, DSM>>>(bA, wbuf, sg1_cb2, bufB, 128, 128,
                                                 sum, sq, nullptr);
    bn_finalize<<<1, 512>>>(sum, sq, sg1_g2, sg1_b2, 1.f/262144.f, 128, ab);
    maxk_kernel<<<1048576/256, 256>>>(bufB, ab, feat1, 128);

    // ---- stage 2 ----
    fps_kernel<<<16, 1024>>>(xyz1, 512, 256, fps2, xyz2);
    knn_kernel<<<dim3(32, 16), 256>>>(xyz2, xyz1, 256, 512, knn2);
    gather2_kernel<<<4096, 256>>>(feat1, fps2, knn2, bA, ctrA);
    wsplit_pair_kernel<<<512, 256>>>(sg2_w1, wr, wc, 256, 128, 512*256);
    // ctr GEMM: [4096, 128] x [512, 128] -> ctrY [4096,512]
    mma_gemm_kernel<<<dim3(4, 32), 256, DSM>>>(ctrA, wc, nullptr, ctrY, 512, 128,
                                               nullptr, nullptr, nullptr);
    mma_gemm_kernel<<<dim3(4, 1024), 256, DSM>>>(bA, wr, sg2_cb1, bufB, 512, 128,
                                                 sum, sq, ctrY);
    bn_finalize<<<1, 512>>>(sum, sq, sg2_g1, sg2_b1, 1.f/131072.f, 512, ab);
    split_bn_kernel<<<131072, 256>>>(bufB, ab, bA, 512, 33554432);
    wsplit_kernel<<<1024, 256>>>(sg2_w2, wbuf, 512, 512*512);
    mma_gemm_kernel<<<dim3(4, 1024), 256, DSM>>>(bA, wbuf, sg2_cb2, bufB, 512, 512,
                                                 sum, sq, nullptr);
    bn_finalize<<<1, 512>>>(sum, sq, sg2_g2, sg2_b2, 1.f/131072.f, 512, ab);
    final_max_kernel<<<2097152/256, 256>>>(bufB, ab, out);
}

// round 11
// speedup vs baseline: 1.2305x; 1.1376x over previous
#include <cuda_runtime.h>
#include <cuda_bf16.h>
#include <cstdint>
#include <cstddef>

#define EPSV 1e-5f

__device__ __forceinline__ uint32_t smem_to_u32(const void* p) {
    uint32_t a;
    asm("{ .reg .u64 t; cvta.to.shared.u64 t, %1; cvt.u32.u64 %0, t; }" : "=r"(a) : "l"(p));
    return a;
}
__device__ __forceinline__ void ldsm4(uint32_t* r, uint32_t addr) {
    asm volatile("ldmatrix.sync.aligned.m8n8.x4.shared.b16 {%0,%1,%2,%3}, [%4];"
        : "=r"(r[0]), "=r"(r[1]), "=r"(r[2]), "=r"(r[3]) : "r"(addr));
}
__device__ __forceinline__ void mma_bf16(float* d, const uint32_t* a, uint32_t b0, uint32_t b1) {
    asm volatile("mma.sync.aligned.m16n8k16.row.col.f32.bf16.bf16.f32 "
        "{%0,%1,%2,%3}, {%4,%5,%6,%7}, {%8,%9}, {%0,%1,%2,%3};"
        : "+f"(d[0]), "+f"(d[1]), "+f"(d[2]), "+f"(d[3])
        : "r"(a[0]), "r"(a[1]), "r"(a[2]), "r"(a[3]), "r"(b0), "r"(b1));
}
__device__ __forceinline__ void split2(float v, __nv_bfloat16& h, __nv_bfloat16& l) {
    h = __float2bfloat16(v);
    l = __float2bfloat16(v - __bfloat162float(h));
}

// ============================ scratch ========================================
__device__ __align__(1024) float g_xyz [16*2048*3];
__device__ __align__(1024) float g_xyz1[16*512*3];
__device__ __align__(1024) float g_xyz2[16*256*3];
__device__ __align__(1024) float g_f0  [16*2048*64];
__device__ __align__(1024) float g_f1r [16*2048*64];
__device__ __align__(1024) float g_feat1[16*512*128];
__device__ int   g_fps1[16*512];
__device__ int   g_fps2[16*256];
__device__ int   g_knn1[16*512*32];
__device__ int   g_knn2[16*256*32];
__device__ float g_sum[512];
__device__ float g_sq [512];
__device__ float g_ab [1024];
__device__ __align__(1024) float g_bufA[67108864];            // 256 MiB
__device__ __align__(1024) float g_bufB[67108864];            // 256 MiB
__device__ __align__(1024) __nv_bfloat16 g_wbuf[512*1024];    // 1 MiB
__device__ __align__(1024) __nv_bfloat16 g_ctrA[1048576];     // 2 MiB
__device__ __align__(1024) float g_ctrY[2097152];             // 8 MiB

// ============================ small kernels ==================================
__global__ void zero_kernel(float* s, float* q, int C) {
    int c = threadIdx.x;
    if (c < C) { s[c] = 0.f; q[c] = 0.f; }
}

__global__ void transpose_xyz_kernel(const float* __restrict__ x, float* __restrict__ xyz)
{
    int p = blockIdx.x * 256 + threadIdx.x;   // 0..32767
    int b = p >> 11, n = p & 2047;
    xyz[p*3+0] = x[(b*3+0)*2048 + n];
    xyz[p*3+1] = x[(b*3+1)*2048 + n];
    xyz[p*3+2] = x[(b*3+2)*2048 + n];
}

// reads stats, emits (a,b), then ZEROES the stats buffers for the next user
__global__ void bn_finalize(float* __restrict__ sum, float* __restrict__ sq,
                            const float* __restrict__ gamma, const float* __restrict__ beta,
                            float inv_count, int C, float* __restrict__ ab)
{
    int c = threadIdx.x;
    if (c < C) {
        float m = sum[c] * inv_count;
        float v = sq[c] * inv_count - m * m;
        v = fmaxf(v, 0.f);
        float a = gamma[c] * rsqrtf(v + EPSV);
        ab[c] = a;
        ab[C + c] = beta[c] - m * a;
    }
    if (c < 512) { sum[c] = 0.f; sq[c] = 0.f; }
}

__global__ void emb1_kernel(const float* __restrict__ x, const float* __restrict__ w,
                            float* __restrict__ f0,
                            float* __restrict__ sum, float* __restrict__ sq)
{
    __shared__ float ws[192];
    __shared__ float csum[64], csq[64];
    int tid = threadIdx.x;
    if (tid < 192) ws[tid] = w[tid];
    if (tid < 64) { csum[tid] = 0.f; csq[tid] = 0.f; }
    __syncthreads();
    int p = blockIdx.x * 256 + tid;
    int b = p >> 11, n = p & 2047;
    float X = x[(b*3+0)*2048 + n];
    float Y = x[(b*3+1)*2048 + n];
    float Z = x[(b*3+2)*2048 + n];
    int lane = tid & 31;
    for (int o = 0; o < 64; o++) {
        float y = X*ws[o*3] + Y*ws[o*3+1] + Z*ws[o*3+2];
        f0[(size_t)p*64 + o] = y;
        float t = y, t2 = y*y;
        #pragma unroll
        for (int off = 16; off > 0; off >>= 1) {
            t  += __shfl_xor_sync(0xffffffffu, t,  off);
            t2 += __shfl_xor_sync(0xffffffffu, t2, off);
        }
        if (lane == 0) { atomicAdd(&csum[o], t); atomicAdd(&csq[o], t2); }
    }
    __syncthreads();
    if (tid < 64) { atomicAdd(&sum[tid], csum[tid]); atomicAdd(&sq[tid], csq[tid]); }
}

// fp32 SIMT GEMM (only used for the tiny emb2 GEMM)
template<int BM, int BN, int BK, int TM, int TN>
__global__ void __launch_bounds__(256, 2) gemm_bn_kernel(
    const float* __restrict__ A, const float* __restrict__ W,
    const float* __restrict__ bias, const float* __restrict__ bnA,
    float* __restrict__ C, int M, int N, int K,
    float* __restrict__ sum, float* __restrict__ sq)
{
    constexpr int NTX = BN / TN;
    __shared__ __align__(16) float As[BK][BM + 4];
    __shared__ __align__(16) float Ws[BK][BN + 4];
    __shared__ float csum[BN], csq[BN];
    int tid = threadIdx.x;
    int tx = tid % NTX, ty = tid / NTX;
    int m0 = blockIdx.x * BM, n0 = blockIdx.y * BN;
    if (tid < BN) { csum[tid] = 0.f; csq[tid] = 0.f; }

    float acc[TM][TN];
    #pragma unroll
    for (int i = 0; i < TM; i++)
        #pragma unroll
        for (int j = 0; j < TN; j++) acc[i][j] = 0.f;

    const int lrow = tid / (BK/4);
    const int lcol = (tid % (BK/4)) * 4;
    constexpr int ROWSTEP = 256 / (BK/4);

    for (int k0 = 0; k0 < K; k0 += BK) {
        #pragma unroll
        for (int r = 0; r < BM; r += ROWSTEP) {
            float4 v = *reinterpret_cast<const float4*>(&A[(size_t)(m0 + r + lrow)*K + k0 + lcol]);
            if (bnA) {
                v.x = fmaxf(bnA[k0+lcol+0]*v.x + bnA[K + k0+lcol+0], 0.f);
                v.y = fmaxf(bnA[k0+lcol+1]*v.y + bnA[K + k0+lcol+1], 0.f);
                v.z = fmaxf(bnA[k0+lcol+2]*v.z + bnA[K + k0+lcol+2], 0.f);
                v.w = fmaxf(bnA[k0+lcol+3]*v.w + bnA[K + k0+lcol+3], 0.f);
            }
            As[lcol+0][r+lrow] = v.x; As[lcol+1][r+lrow] = v.y;
            As[lcol+2][r+lrow] = v.z; As[lcol+3][r+lrow] = v.w;
        }
        #pragma unroll
        for (int r = 0; r < BN; r += ROWSTEP) {
            float4 v = *reinterpret_cast<const float4*>(&W[(size_t)(n0 + r + lrow)*K + k0 + lcol]);
            Ws[lcol+0][r+lrow] = v.x; Ws[lcol+1][r+lrow] = v.y;
            Ws[lcol+2][r+lrow] = v.z; Ws[lcol+3][r+lrow] = v.w;
        }
        __syncthreads();
        #pragma unroll
        for (int kk = 0; kk < BK; kk++) {
            float af[TM], wf[TN];
            #pragma unroll
            for (int i = 0; i < TM; i += 4) {
                float4 t = *reinterpret_cast<const float4*>(&As[kk][ty*TM + i]);
                af[i] = t.x; af[i+1] = t.y; af[i+2] = t.z; af[i+3] = t.w;
            }
            #pragma unroll
            for (int j = 0; j < TN; j += 4) {
                float4 t = *reinterpret_cast<const float4*>(&Ws[kk][tx*TN + j]);
                wf[j] = t.x; wf[j+1] = t.y; wf[j+2] = t.z; wf[j+3] = t.w;
            }
            #pragma unroll
            for (int i = 0; i < TM; i++)
                #pragma unroll
                for (int j = 0; j < TN; j++)
                    acc[i][j] = fmaf(af[i], wf[j], acc[i][j]);
        }
        __syncthreads();
    }
    #pragma unroll
    for (int j = 0; j < TN; j++) {
        int n = n0 + tx*TN + j;
        float bsv = bias ? bias[n] : 0.f;
        float s_ = 0.f, q_ = 0.f;
        #pragma unroll
        for (int i = 0; i < TM; i++) {
            float y = acc[i][j] + bsv;
            acc[i][j] = y;
            s_ += y; q_ += y*y;
        }
        atomicAdd(&csum[tx*TN + j], s_);
        atomicAdd(&csq [tx*TN + j], q_);
    }
    #pragma unroll
    for (int i = 0; i < TM; i++) {
        #pragma unroll
        for (int j = 0; j < TN; j += 4) {
            float4 v = make_float4(acc[i][j], acc[i][j+1], acc[i][j+2], acc[i][j+3]);
            *reinterpret_cast<float4*>(&C[(size_t)(m0 + ty*TM + i)*N + n0 + tx*TN + j]) = v;
        }
    }
    __syncthreads();
    if (tid < BN) {
        atomicAdd(&sum[n0 + tid], csum[tid]);
        atomicAdd(&sq [n0 + tid], csq[tid]);
    }
}

// ============ HMMA bf16 split-precision GEMM, 1-sync pipelined ===============
__device__ __forceinline__ void gemm_issue_chunk(
    const __nv_bfloat16* __restrict__ A, const __nv_bfloat16* __restrict__ W,
    size_t m0, int n0, int K, int K2, uint32_t u0, int tid, int ch, int nch)
{
    if (ch < nch) {
        uint32_t sb = u0 + (uint32_t)(ch % 3) * 32768u;
        int k0 = ch * 32;
        #pragma unroll
        for (int i = 0; i < 8; i++) {
            int idx = i * 256 + tid;          // 0..2047
            int buf = idx >> 9;               // 0:Ahi 1:Alo 2:Whi 3:Wlo
            int r = (idx >> 2) & 127;
            int c16 = idx & 3;
            uint32_t dst = sb + (uint32_t)buf * 8192u
                         + (((uint32_t)(r * 64 + c16 * 16)) ^ (((uint32_t)(r & 6)) << 3));
            const __nv_bfloat16* src;
            if (buf == 0)      src = A + (m0 + r) * K2 + k0 + c16 * 8;
            else if (buf == 1) src = A + (m0 + r) * K2 + K + k0 + c16 * 8;
            else if (buf == 2) src = W + ((size_t)(n0 + r)) * K2 + k0 + c16 * 8;
            else               src = W + ((size_t)(n0 + r)) * K2 + K + k0 + c16 * 8;
            asm volatile("cp.async.cg.shared.global [%0], [%1], 16;" :: "r"(dst), "l"(src));
        }
    }
    asm volatile("cp.async.commit_group;" ::: "memory");
}

extern __shared__ unsigned char dynsm[];

__global__ void __launch_bounds__(256, 2) mma_gemm_kernel(
    const __nv_bfloat16* __restrict__ A, const __nv_bfloat16* __restrict__ W,
    const float* __restrict__ bias, float* __restrict__ C,
    int N, int K, float* __restrict__ gsum, float* __restrict__ gsq,
    const float* __restrict__ rowAdd)
{
    float* sbias = (float*)(dynsm + 98304);
    float* csum  = sbias + 128;
    float* csq   = csum + 128;

    int tid = threadIdx.x, wid = tid >> 5, lane = tid & 31;
    int n0 = blockIdx.x * 128;
    size_t m0 = (size_t)blockIdx.y * 128;
    int K2 = 2 * K;
    if (tid < 128) {
        sbias[tid] = bias ? bias[n0 + tid] : 0.f;
        csum[tid] = 0.f; csq[tid] = 0.f;
    }

    int wm = (wid & 1) * 64;
    int wn = (wid >> 1) * 32;

    float acc[4][4][4];
    #pragma unroll
    for (int mi = 0; mi < 4; mi++)
        #pragma unroll
        for (int ni = 0; ni < 4; ni++)
            #pragma unroll
            for (int j = 0; j < 4; j++) acc[mi][ni][j] = 0.f;

    uint32_t u0 = smem_to_u32(dynsm);
    int g = lane >> 3, lr = lane & 7;
    uint32_t sw = ((uint32_t)(lr & 6)) << 3;
    uint32_t arow = (uint32_t)((wm + (g & 1) * 8 + lr) * 64);
    uint32_t acol = (uint32_t)((g >> 1) * 16);
    uint32_t brow = (uint32_t)((wn + (g >> 1) * 8 + lr) * 64);
    uint32_t bcol = (uint32_t)((g & 1) * 16);

    const int nch = K >> 5;
    gemm_issue_chunk(A, W, m0, n0, K, K2, u0, tid, 0, nch);
    gemm_issue_chunk(A, W, m0, n0, K, K2, u0, tid, 1, nch);

    for (int ch = 0; ch < nch; ch++) {
        asm volatile("cp.async.wait_group 1;" ::: "memory");
        __syncthreads();
        gemm_issue_chunk(A, W, m0, n0, K, K2, u0, tid, ch + 2, nch);
        uint32_t sb = u0 + (uint32_t)(ch % 3) * 32768u;
        #pragma unroll
        for (int kk = 0; kk < 2; kk++) {
            uint32_t kb = (uint32_t)(kk * 32);
            uint32_t af_hi[4][4], bf_hi[2][4];
            #pragma unroll
            for (int mi = 0; mi < 4; mi++)
                ldsm4(af_hi[mi], sb + arow + (uint32_t)(mi * 1024) + ((kb + acol) ^ sw));
            #pragma unroll
            for (int bi = 0; bi < 2; bi++)
                ldsm4(bf_hi[bi], sb + 16384u + brow + (uint32_t)(bi * 1024) + ((kb + bcol) ^ sw));
            #pragma unroll
            for (int mi = 0; mi < 4; mi++)
                #pragma unroll
                for (int ni = 0; ni < 4; ni++)
                    mma_bf16(acc[mi][ni], af_hi[mi],
                             bf_hi[ni >> 1][(ni & 1) * 2], bf_hi[ni >> 1][(ni & 1) * 2 + 1]);
            {
                uint32_t bf_lo[2][4];
                #pragma unroll
                for (int bi = 0; bi < 2; bi++)
                    ldsm4(bf_lo[bi], sb + 24576u + brow + (uint32_t)(bi * 1024) + ((kb + bcol) ^ sw));
                #pragma unroll
                for (int mi = 0; mi < 4; mi++)
                    #pragma unroll
                    for (int ni = 0; ni < 4; ni++)
                        mma_bf16(acc[mi][ni], af_hi[mi],
                                 bf_lo[ni >> 1][(ni & 1) * 2], bf_lo[ni >> 1][(ni & 1) * 2 + 1]);
            }
            {
                uint32_t af_lo[4][4];
                #pragma unroll
                for (int mi = 0; mi < 4; mi++)
                    ldsm4(af_lo[mi], sb + 8192u + arow + (uint32_t)(mi * 1024) + ((kb + acol) ^ sw));
                #pragma unroll
                for (int mi = 0; mi < 4; mi++)
                    #pragma unroll
                    for (int ni = 0; ni < 4; ni++)
                        mma_bf16(acc[mi][ni], af_lo[mi],
                                 bf_hi[ni >> 1][(ni & 1) * 2], bf_hi[ni >> 1][(ni & 1) * 2 + 1]);
            }
        }
    }
    __syncthreads();

    // epilogue: bias, rowAdd, stats, store
    int r = lane >> 2, c2 = (lane & 3) << 1;
    float cs[8], cq[8];
    #pragma unroll
    for (int s = 0; s < 8; s++) { cs[s] = 0.f; cq[s] = 0.f; }
    #pragma unroll
    for (int mi = 0; mi < 4; mi++) {
        #pragma unroll
        for (int ni = 0; ni < 4; ni++) {
            int col = wn + ni * 8 + c2;
            float b0v = sbias[col], b1v = sbias[col + 1];
            size_t row = m0 + wm + mi * 16 + r;
            float a00 = 0.f, a01 = 0.f, a10 = 0.f, a11 = 0.f;
            if (rowAdd) {
                const float* r0p = rowAdd + (row >> 5) * (size_t)N + n0 + col;
                const float* r1p = rowAdd + ((row + 8) >> 5) * (size_t)N + n0 + col;
                a00 = r0p[0]; a01 = r0p[1];
                a10 = r1p[0]; a11 = r1p[1];
            }
            float v00 = acc[mi][ni][0] + b0v + a00, v01 = acc[mi][ni][1] + b1v + a01;
            float v10 = acc[mi][ni][2] + b0v + a10, v11 = acc[mi][ni][3] + b1v + a11;
            *reinterpret_cast<float2*>(&C[row * (size_t)N + n0 + col]) = make_float2(v00, v01);
            *reinterpret_cast<float2*>(&C[(row + 8) * (size_t)N + n0 + col]) = make_float2(v10, v11);
            cs[ni*2]   += v00 + v10;  cs[ni*2+1] += v01 + v11;
            cq[ni*2]   += v00*v00 + v10*v10;
            cq[ni*2+1] += v01*v01 + v11*v11;
        }
    }
    if (gsum) {
        #pragma unroll
        for (int s = 0; s < 8; s++) {
            float v = cs[s], q = cq[s];
            #pragma unroll
            for (int o = 4; o <= 16; o <<= 1) {
                v += __shfl_xor_sync(0xffffffffu, v, o);
                q += __shfl_xor_sync(0xffffffffu, q, o);
            }
            if (lane < 4) {
                int col = wn + (s >> 1) * 8 + lane * 2 + (s & 1);
                atomicAdd(&csum[col], v);
                atomicAdd(&csq[col], q);
            }
        }
        __syncthreads();
        if (tid < 128) {
            atomicAdd(&gsum[n0 + tid], csum[tid]);
            atomicAdd(&gsq [n0 + tid], csq[tid]);
        }
    }
}

// ---------------- FPS (1024 threads, R8-proven two-barrier variant) ----------
__global__ void __launch_bounds__(1024) fps_kernel(
    const float* __restrict__ xyz, int N, int S,
    int* __restrict__ idx_out, float* __restrict__ xyz_out)
{
    __shared__ float px[2048], py[2048], pz[2048], dist[2048];
    __shared__ float rv[32];
    __shared__ int   ri[32];
    __shared__ int   selv;
    __shared__ int   sidx[512];
    int b = blockIdx.x, tid = threadIdx.x, lane = tid & 31, wid = tid >> 5;
    for (int i = tid; i < N; i += 1024) {
        px[i] = xyz[(b*N + i)*3 + 0];
        py[i] = xyz[(b*N + i)*3 + 1];
        pz[i] = xyz[(b*N + i)*3 + 2];
        dist[i] = 1e10f;
    }
    __syncthreads();
    int sel = 0;
    for (int it = 0; it < S; it++) {
        if (tid == 0) sidx[it] = sel;
        float sx = px[sel], sy = py[sel], sz = pz[sel];
        float bv = -1.f; int bi = 0x7fffffff;
        for (int j = tid; j < N; j += 1024) {
            float dx = px[j]-sx, dy = py[j]-sy, dz = pz[j]-sz;
            float d = dx*dx + dy*dy + dz*dz;
            float nd = fminf(dist[j], d);
            dist[j] = nd;
            if (nd > bv) { bv = nd; bi = j; }
        }
        #pragma unroll
        for (int o = 16; o > 0; o >>= 1) {
            float ov = __shfl_xor_sync(0xffffffffu, bv, o);
            int   oi = __shfl_xor_sync(0xffffffffu, bi, o);
            if (ov > bv || (ov == bv && oi < bi)) { bv = ov; bi = oi; }
        }
        if (lane == 0) { rv[wid] = bv; ri[wid] = bi; }
        __syncthreads();
        if (tid < 32) {
            float v = rv[lane];
            int  ii = ri[lane];
            #pragma unroll
            for (int o = 16; o > 0; o >>= 1) {
                float ov = __shfl_xor_sync(0xffffffffu, v, o);
                int   oi = __shfl_xor_sync(0xffffffffu, ii, o);
                if (ov > v || (ov == v && oi < ii)) { v = ov; ii = oi; }
            }
            if (lane == 0) selv = ii;
        }
        __syncthreads();
        sel = selv;
    }
    for (int s = tid; s < S; s += 1024) {
        int i = sidx[s];
        idx_out[b*S + s] = i;
        xyz_out[(b*S + s)*3 + 0] = px[i];
        xyz_out[(b*S + s)*3 + 1] = py[i];
        xyz_out[(b*S + s)*3 + 2] = pz[i];
    }
}

// ---------------- kNN (k=32) -------------------------------------------------
__global__ void knn_kernel(const float* __restrict__ q_xyz, const float* __restrict__ c_xyz,
                           int S, int N, int* __restrict__ knn)
{
    __shared__ float cx[2048], cy[2048], cz[2048];
    int b = blockIdx.y, tid = threadIdx.x;
    for (int i = tid; i < N; i += blockDim.x) {
        cx[i] = c_xyz[(b*N + i)*3 + 0];
        cy[i] = c_xyz[(b*N + i)*3 + 1];
        cz[i] = c_xyz[(b*N + i)*3 + 2];
    }
    __syncthreads();
    int warp = tid >> 5, lane = tid & 31;
    int q = blockIdx.x * (blockDim.x >> 5) + warp;
    if (q >= S) return;
    float qx = q_xyz[(b*S+q)*3+0], qy = q_xyz[(b*S+q)*3+1], qz = q_xyz[(b*S+q)*3+2];
    float topd = 3.4e38f; int topi = 0;
    float curmax = 3.4e38f;
    for (int c0 = 0; c0 < N; c0 += 32) {
        int c = c0 + lane;
        float dx = cx[c]-qx, dy = cy[c]-qy, dz = cz[c]-qz;
        float d = dx*dx + dy*dy + dz*dz;
        unsigned bal = __ballot_sync(0xffffffffu, d < curmax);
        while (bal) {
            int src = __ffs(bal) - 1; bal &= bal - 1;
            float dv = __shfl_sync(0xffffffffu, d, src);
            float mv = topd; int ml = lane;
            #pragma unroll
            for (int off = 16; off > 0; off >>= 1) {
                float ov = __shfl_xor_sync(0xffffffffu, mv, off);
                int   ol = __shfl_xor_sync(0xffffffffu, ml, off);
                if (ov > mv || (ov == mv && ol < ml)) { mv = ov; ml = ol; }
            }
            if (dv < mv && lane == ml) { topd = dv; topi = c0 + src; }
            curmax = mv;
        }
    }
    knn[(b*S + q)*32 + lane] = topi;
}

// ---------------- gathers (rel-only rows + separate ctr buffer) --------------
__global__ void gather1_kernel(const float* __restrict__ f1raw, const int* __restrict__ fps,
                               const int* __restrict__ knn, const float* __restrict__ ab,
                               __nv_bfloat16* __restrict__ relA, __nv_bfloat16* __restrict__ ctrA)
{
    int bs = blockIdx.x;           // b*512+s
    int b = bs >> 9;
    __shared__ float ctr[64];
    int tid = threadIdx.x;
    if (tid < 64) {
        int ci = fps[bs];
        float v = f1raw[(size_t)(b*2048 + ci)*64 + tid];
        v = fmaxf(ab[tid]*v + ab[64+tid], 0.f);
        ctr[tid] = v;
        __nv_bfloat16 h, l; split2(v, h, l);
        ctrA[(size_t)bs*128 + tid] = h;
        ctrA[(size_t)bs*128 + 64 + tid] = l;
    }
    __syncthreads();
    for (int e = tid; e < 32*64; e += 256) {
        int k = e >> 6, c = e & 63;
        int ni = knn[bs*32 + k];
        float v = f1raw[(size_t)(b*2048 + ni)*64 + c];
        v = fmaxf(ab[c]*v + ab[64+c], 0.f) - ctr[c];
        __nv_bfloat16 h, l; split2(v, h, l);
        __nv_bfloat16* p = relA + ((size_t)bs*32 + k) * 128;
        p[c] = h;
        p[64 + c] = l;
    }
}

__global__ void gather2_kernel(const float* __restrict__ feat, const int* __restrict__ fps,
                               const int* __restrict__ knn,
                               __nv_bfloat16* __restrict__ relA, __nv_bfloat16* __restrict__ ctrA)
{
    int bs = blockIdx.x;           // b*256+s
    int b = bs >> 8;
    __shared__ float ctr[128];
    int tid = threadIdx.x;
    if (tid < 128) {
        int ci = fps[bs];
        float v = feat[(size_t)(b*512 + ci)*128 + tid];
        ctr[tid] = v;
        __nv_bfloat16 h, l; split2(v, h, l);
        ctrA[(size_t)bs*256 + tid] = h;
        ctrA[(size_t)bs*256 + 128 + tid] = l;
    }
    __syncthreads();
    for (int e = tid; e < 32*128; e += 256) {
        int k = e >> 7, c = e & 127;
        int ni = knn[bs*32 + k];
        float v = feat[(size_t)(b*512 + ni)*128 + c] - ctr[c];
        __nv_bfloat16 h, l; split2(v, h, l);
        __nv_bfloat16* p = relA + ((size_t)bs*32 + k) * 256;
        p[c] = h;
        p[128 + c] = l;
    }
}

// BN+ReLU + hi/lo split of a raw GEMM output: X[M,C] -> O[M,2C]
__global__ void split_bn_kernel(const float* __restrict__ X, const float* __restrict__ ab,
                                __nv_bfloat16* __restrict__ O, int C, int total_half)
{
    int i = blockIdx.x * 256 + threadIdx.x;
    if (i >= total_half) return;
    int hc = C >> 1;
    int row = i / hc;
    int c = (i - row * hc) * 2;
    float2 v = *reinterpret_cast<const float2*>(&X[(size_t)row * C + c]);
    float y0 = fmaxf(ab[c]   * v.x + ab[C + c],     0.f);
    float y1 = fmaxf(ab[c+1] * v.y + ab[C + c + 1], 0.f);
    __nv_bfloat16 h0, l0, h1, l1;
    split2(y0, h0, l0); split2(y1, h1, l1);
    __nv_bfloat162 hh; hh.x = h0; hh.y = h1;
    __nv_bfloat162 ll; ll.x = l0; ll.y = l1;
    *reinterpret_cast<__nv_bfloat162*>(&O[(size_t)row * 2 * C + c]) = hh;
    *reinterpret_cast<__nv_bfloat162*>(&O[(size_t)row * 2 * C + C + c]) = ll;
}

// weight split fp32 [N,K] -> bf16 [N,2K] = [hi|lo]
__global__ void wsplit_kernel(const float* __restrict__ W, __nv_bfloat16* __restrict__ O,
                              int K, int total)
{
    int i = blockIdx.x * 256 + threadIdx.x;
    if (i >= total) return;
    int row = i / K, c = i - row * K;
    __nv_bfloat16 h, l; split2(W[i], h, l);
    O[(size_t)row * 2 * K + c] = h;
    O[(size_t)row * 2 * K + K + c] = l;
}

// weight pair split: W [N, K] with K = 2*Khalf = [rel|ctr] columns
__global__ void wsplit_pair_kernel(const float* __restrict__ W,
                                   __nv_bfloat16* __restrict__ Wr,
                                   __nv_bfloat16* __restrict__ Wc,
                                   int K, int Khalf, int total)
{
    int i = blockIdx.x * 256 + threadIdx.x;
    if (i >= total) return;
    int row = i / K, c = i - row * K;
    __nv_bfloat16 h, l; split2(W[i], h, l);
    if (c < Khalf) {
        Wr[(size_t)row * 2 * Khalf + c] = h;
        Wr[(size_t)row * 2 * Khalf + Khalf + c] = l;
    } else {
        int cc = c - Khalf;
        Wc[(size_t)row * 2 * Khalf + cc] = h;
        Wc[(size_t)row * 2 * Khalf + Khalf + cc] = l;
    }
}

// fused BN+relu+max over k
__global__ void maxk_kernel(const float* __restrict__ h, const float* __restrict__ ab,
                            float* __restrict__ out, int C)
{
    int idx = blockIdx.x * blockDim.x + threadIdx.x;
    int q = idx / C, o = idx - q*C;
    float mx = -3.4e38f, mn = 3.4e38f;
    for (int k = 0; k < 32; k++) {
        float v = h[(size_t)(q*32 + k)*C + o];
        mx = fmaxf(mx, v); mn = fminf(mn, v);
    }
    float a = ab[o];
    float e = (a >= 0.f) ? mx : mn;
    out[idx] = fmaxf(a*e + ab[C+o], 0.f);
}

__global__ void final_max_kernel(const float* __restrict__ h, const float* __restrict__ ab,
                                 float* __restrict__ out)
{
    int idx = blockIdx.x * blockDim.x + threadIdx.x;  // 16*256*512
    int o = idx & 511; int q = idx >> 9; int b = q >> 8, s = q & 255;
    float mx = -3.4e38f, mn = 3.4e38f;
    for (int k = 0; k < 32; k++) {
        float v = h[(size_t)(q*32 + k)*512 + o];
        mx = fmaxf(mx, v); mn = fminf(mn, v);
    }
    float a = ab[o];
    float e = (a >= 0.f) ? mx : mn;
    out[(size_t)(b*512 + o)*256 + s] = fmaxf(a*e + ab[512+o], 0.f);
}

// ============================ driver =========================================
extern "C" void kernel_launch(void* const* d_in, const int* in_sizes, int n_in,
                              void* d_out, int out_size)
{
    const float* x       = (const float*)d_in[0];
    const float* emb_w1  = (const float*)d_in[1];
    const float* emb_g1  = (const float*)d_in[2];
    const float* emb_b1  = (const float*)d_in[3];
    const float* emb_w2  = (const float*)d_in[4];
    const float* emb_g2  = (const float*)d_in[5];
    const float* emb_b2  = (const float*)d_in[6];
    const float* sg1_w1  = (const float*)d_in[7];
    const float* sg1_cb1 = (const float*)d_in[8];
    const float* sg1_g1  = (const float*)d_in[9];
    const float* sg1_b1  = (const float*)d_in[10];
    const float* sg1_w2  = (const float*)d_in[11];
    const float* sg1_cb2 = (const float*)d_in[12];
    const float* sg1_g2  = (const float*)d_in[13];
    const float* sg1_b2  = (const float*)d_in[14];
    const float* sg2_w1  = (const float*)d_in[15];
    const float* sg2_cb1 = (const float*)d_in[16];
    const float* sg2_g1  = (const float*)d_in[17];
    const float* sg2_b1  = (const float*)d_in[18];
    const float* sg2_w2  = (const float*)d_in[19];
    const float* sg2_cb2 = (const float*)d_in[20];
    const float* sg2_g2  = (const float*)d_in[21];
    const float* sg2_b2  = (const float*)d_in[22];
    float* out = (float*)d_out;

    float *xyz, *xyz1, *xyz2, *f0, *f1r, *feat1, *sum, *sq, *ab, *bufA, *bufB, *ctrY;
    __nv_bfloat16 *wbuf, *ctrA;
    int *fps1, *fps2, *knn1, *knn2;
    cudaGetSymbolAddress((void**)&xyz,   g_xyz);
    cudaGetSymbolAddress((void**)&xyz1,  g_xyz1);
    cudaGetSymbolAddress((void**)&xyz2,  g_xyz2);
    cudaGetSymbolAddress((void**)&f0,    g_f0);
    cudaGetSymbolAddress((void**)&f1r,   g_f1r);
    cudaGetSymbolAddress((void**)&feat1, g_feat1);
    cudaGetSymbolAddress((void**)&sum,   g_sum);
    cudaGetSymbolAddress((void**)&sq,    g_sq);
    cudaGetSymbolAddress((void**)&ab,    g_ab);
    cudaGetSymbolAddress((void**)&bufA,  g_bufA);
    cudaGetSymbolAddress((void**)&bufB,  g_bufB);
    cudaGetSymbolAddress((void**)&wbuf,  g_wbuf);
    cudaGetSymbolAddress((void**)&ctrA,  g_ctrA);
    cudaGetSymbolAddress((void**)&ctrY,  g_ctrY);
    cudaGetSymbolAddress((void**)&fps1,  g_fps1);
    cudaGetSymbolAddress((void**)&fps2,  g_fps2);
    cudaGetSymbolAddress((void**)&knn1,  g_knn1);
    cudaGetSymbolAddress((void**)&knn2,  g_knn2);

    cudaFuncSetAttribute(mma_gemm_kernel,
                         cudaFuncAttributeMaxDynamicSharedMemorySize, 99840);
    const int DSM = 99840;

    // side stream + fork/join events (created per call, never destroyed:
    // destroying a stream participating in an active capture invalidates it;
    // kernel_launch runs only twice so the leak is bounded and harmless)
    cudaStream_t s_side;
    cudaStreamCreateWithFlags(&s_side, cudaStreamNonBlocking);
    cudaEvent_t ev0, ev1, ev2;
    cudaEventCreateWithFlags(&ev0, cudaEventDisableTiming);
    cudaEventCreateWithFlags(&ev1, cudaEventDisableTiming);
    cudaEventCreateWithFlags(&ev2, cudaEventDisableTiming);

    __nv_bfloat16* bA = (__nv_bfloat16*)bufA;
    __nv_bfloat16* wr = wbuf;
    __nv_bfloat16* wc = wbuf + 262144;

    // ---- transpose, then fork geometry pipeline onto side stream ----
    transpose_xyz_kernel<<<128, 256>>>(x, xyz);
    cudaEventRecord(ev0, 0);
    cudaStreamWaitEvent(s_side, ev0, 0);
    fps_kernel<<<16, 1024, 0, s_side>>>(xyz, 2048, 512, fps1, xyz1);
    knn_kernel<<<dim3(64, 16), 256, 0, s_side>>>(xyz1, xyz, 512, 2048, knn1);
    cudaEventRecord(ev1, s_side);
    fps_kernel<<<16, 1024, 0, s_side>>>(xyz1, 512, 256, fps2, xyz2);
    knn_kernel<<<dim3(32, 16), 256, 0, s_side>>>(xyz2, xyz1, 256, 512, knn2);
    cudaEventRecord(ev2, s_side);

    // ---- embedding (main stream, concurrent with fps/knn) ----
    zero_kernel<<<1, 512>>>(sum, sq, 512);
    emb1_kernel<<<128, 256>>>(x, emb_w1, f0, sum, sq);
    bn_finalize<<<1, 512>>>(sum, sq, emb_g1, emb_b1, 1.f/32768.f, 64, ab);
    gemm_bn_kernel<128,64,16,8,4><<<dim3(256, 1), 256>>>(f0, emb_w2, nullptr, ab, f1r,
                                                         32768, 64, 64, sum, sq);
    bn_finalize<<<1, 512>>>(sum, sq, emb_g2, emb_b2, 1.f/32768.f, 64, ab);

    // ---- stage 1 (needs fps1/knn1) ----
    cudaStreamWaitEvent(0, ev1, 0);
    gather1_kernel<<<8192, 256>>>(f1r, fps1, knn1, ab, bA, ctrA);
    wsplit_pair_kernel<<<64, 256>>>(sg1_w1, wr, wc, 128, 64, 128*128);
    mma_gemm_kernel<<<dim3(1, 64), 256, DSM>>>(ctrA, wc, nullptr, ctrY, 128, 64,
                                               nullptr, nullptr, nullptr);
    mma_gemm_kernel<<<dim3(1, 2048), 256, DSM>>>(bA, wr, sg1_cb1, bufB, 128, 64,
                                                 sum, sq, ctrY);
    bn_finalize<<<1, 512>>>(sum, sq, sg1_g1, sg1_b1, 1.f/262144.f, 128, ab);
    split_bn_kernel<<<65536, 256>>>(bufB, ab, bA, 128, 16777216);
    wsplit_kernel<<<64, 256>>>(sg1_w2, wbuf, 128, 128*128);
    mma_gemm_kernel<<<dim3(1, 2048), 256, DSM>>>(bA, wbuf, sg1_cb2, bufB, 128, 128,
                                                 sum, sq, nullptr);
    bn_finalize<<<1, 512>>>(sum, sq, sg1_g2, sg1_b2, 1.f/262144.f, 128, ab);
    maxk_kernel<<<1048576/256, 256>>>(bufB, ab, feat1, 128);

    // ---- stage 2 (needs fps2/knn2) ----
    cudaStreamWaitEvent(0, ev2, 0);
    gather2_kernel<<<4096, 256>>>(feat1, fps2, knn2, bA, ctrA);
    wsplit_pair_kernel<<<512, 256>>>(sg2_w1, wr, wc, 256, 128, 512*256);
    mma_gemm_kernel<<<dim3(4, 32), 256, DSM>>>(ctrA, wc, nullptr, ctrY, 512, 128,
                                               nullptr, nullptr, nullptr);
    mma_gemm_kernel<<<dim3(4, 1024), 256, DSM>>>(bA, wr, sg2_cb1, bufB, 512, 128,
                                                 sum, sq, ctrY);
    bn_finalize<<<1, 512>>>(sum, sq, sg2_g1, sg2_b1, 1.f/131072.f, 512, ab);
    split_bn_kernel<<<131072, 256>>>(bufB, ab, bA, 512, 33554432);
    wsplit_kernel<<<1024, 256>>>(sg2_w2, wbuf, 512, 512*512);
    mma_gemm_kernel<<<dim3(4, 1024), 256, DSM>>>(bA, wbuf, sg2_cb2, bufB, 512, 512,
                                                 sum, sq, nullptr);
    bn_finalize<<<1, 512>>>(sum, sq, sg2_g2, sg2_b2, 1.f/131072.f, 512, ab);
    final_max_kernel<<<2097152/256, 256>>>(bufB, ab, out);
}

// round 15
// speedup vs baseline: 1.3600x; 1.1053x over previous
#include <cuda_runtime.h>
#include <cuda_bf16.h>
#include <cstdint>
#include <cstddef>

#define EPSV 1e-5f

__device__ __forceinline__ uint32_t smem_to_u32(const void* p) {
    uint32_t a;
    asm("{ .reg .u64 t; cvta.to.shared.u64 t, %1; cvt.u32.u64 %0, t; }" : "=r"(a) : "l"(p));
    return a;
}
__device__ __forceinline__ void ldsm4(uint32_t* r, uint32_t addr) {
    asm volatile("ldmatrix.sync.aligned.m8n8.x4.shared.b16 {%0,%1,%2,%3}, [%4];"
        : "=r"(r[0]), "=r"(r[1]), "=r"(r[2]), "=r"(r[3]) : "r"(addr));
}
__device__ __forceinline__ void mma_bf16(float* d, const uint32_t* a, uint32_t b0, uint32_t b1) {
    asm volatile("mma.sync.aligned.m16n8k16.row.col.f32.bf16.bf16.f32 "
        "{%0,%1,%2,%3}, {%4,%5,%6,%7}, {%8,%9}, {%0,%1,%2,%3};"
        : "+f"(d[0]), "+f"(d[1]), "+f"(d[2]), "+f"(d[3])
        : "r"(a[0]), "r"(a[1]), "r"(a[2]), "r"(a[3]), "r"(b0), "r"(b1));
}
__device__ __forceinline__ void split2(float v, __nv_bfloat16& h, __nv_bfloat16& l) {
    h = __float2bfloat16(v);
    l = __float2bfloat16(v - __bfloat162float(h));
}

// ============================ scratch ========================================
__device__ __align__(1024) float g_xyz [16*2048*3];
__device__ __align__(1024) float g_xyz1[16*512*3];
__device__ __align__(1024) float g_xyz2[16*256*3];
__device__ __align__(1024) float g_f0  [16*2048*64];
__device__ __align__(1024) float g_f1r [16*2048*64];
__device__ __align__(1024) float g_feat1[16*512*128];
__device__ int   g_fps1[16*512];
__device__ int   g_fps2[16*256];
__device__ int   g_knn1[16*512*32];
__device__ int   g_knn2[16*256*32];
__device__ float g_sum[512];
__device__ float g_sq [512];
__device__ float g_ab [1024];
__device__ __align__(1024) float g_bufA[67108864];            // 256 MiB
__device__ __align__(1024) float g_bufB[67108864];            // 256 MiB
__device__ __align__(1024) __nv_bfloat16 g_wbuf[512*1024];    // 1 MiB
__device__ __align__(1024) __nv_bfloat16 g_ctrA[1048576];     // 2 MiB
__device__ __align__(1024) float g_ctrY[2097152];             // 8 MiB
__device__ __align__(1024) float g_extM[2097152];             // 8 MiB (per-query max)
__device__ __align__(1024) float g_extN[2097152];             // 8 MiB (per-query min)

// ============================ small kernels ==================================
__global__ void zero_kernel(float* s, float* q, int C) {
    int c = threadIdx.x;
    if (c < C) { s[c] = 0.f; q[c] = 0.f; }
}

__global__ void transpose_xyz_kernel(const float* __restrict__ x, float* __restrict__ xyz)
{
    int p = blockIdx.x * 256 + threadIdx.x;
    int b = p >> 11, n = p & 2047;
    xyz[p*3+0] = x[(b*3+0)*2048 + n];
    xyz[p*3+1] = x[(b*3+1)*2048 + n];
    xyz[p*3+2] = x[(b*3+2)*2048 + n];
}

__global__ void bn_finalize(float* __restrict__ sum, float* __restrict__ sq,
                            const float* __restrict__ gamma, const float* __restrict__ beta,
                            float inv_count, int C, float* __restrict__ ab)
{
    int c = threadIdx.x;
    if (c < C) {
        float m = sum[c] * inv_count;
        float v = sq[c] * inv_count - m * m;
        v = fmaxf(v, 0.f);
        float a = gamma[c] * rsqrtf(v + EPSV);
        ab[c] = a;
        ab[C + c] = beta[c] - m * a;
    }
    if (c < 512) { sum[c] = 0.f; sq[c] = 0.f; }
}

__global__ void emb1_kernel(const float* __restrict__ x, const float* __restrict__ w,
                            float* __restrict__ f0,
                            float* __restrict__ sum, float* __restrict__ sq)
{
    __shared__ float ws[192];
    __shared__ float csum[64], csq[64];
    int tid = threadIdx.x;
    if (tid < 192) ws[tid] = w[tid];
    if (tid < 64) { csum[tid] = 0.f; csq[tid] = 0.f; }
    __syncthreads();
    int p = blockIdx.x * 256 + tid;
    int b = p >> 11, n = p & 2047;
    float X = x[(b*3+0)*2048 + n];
    float Y = x[(b*3+1)*2048 + n];
    float Z = x[(b*3+2)*2048 + n];
    int lane = tid & 31;
    for (int o = 0; o < 64; o++) {
        float y = X*ws[o*3] + Y*ws[o*3+1] + Z*ws[o*3+2];
        f0[(size_t)p*64 + o] = y;
        float t = y, t2 = y*y;
        #pragma unroll
        for (int off = 16; off > 0; off >>= 1) {
            t  += __shfl_xor_sync(0xffffffffu, t,  off);
            t2 += __shfl_xor_sync(0xffffffffu, t2, off);
        }
        if (lane == 0) { atomicAdd(&csum[o], t); atomicAdd(&csq[o], t2); }
    }
    __syncthreads();
    if (tid < 64) { atomicAdd(&sum[tid], csum[tid]); atomicAdd(&sq[tid], csq[tid]); }
}

// fp32 SIMT GEMM (only used for the tiny emb2 GEMM)
template<int BM, int BN, int BK, int TM, int TN>
__global__ void __launch_bounds__(256, 2) gemm_bn_kernel(
    const float* __restrict__ A, const float* __restrict__ W,
    const float* __restrict__ bias, const float* __restrict__ bnA,
    float* __restrict__ C, int M, int N, int K,
    float* __restrict__ sum, float* __restrict__ sq)
{
    constexpr int NTX = BN / TN;
    __shared__ __align__(16) float As[BK][BM + 4];
    __shared__ __align__(16) float Ws[BK][BN + 4];
    __shared__ float csum[BN], csq[BN];
    int tid = threadIdx.x;
    int tx = tid % NTX, ty = tid / NTX;
    int m0 = blockIdx.x * BM, n0 = blockIdx.y * BN;
    if (tid < BN) { csum[tid] = 0.f; csq[tid] = 0.f; }

    float acc[TM][TN];
    #pragma unroll
    for (int i = 0; i < TM; i++)
        #pragma unroll
        for (int j = 0; j < TN; j++) acc[i][j] = 0.f;

    const int lrow = tid / (BK/4);
    const int lcol = (tid % (BK/4)) * 4;
    constexpr int ROWSTEP = 256 / (BK/4);

    for (int k0 = 0; k0 < K; k0 += BK) {
        #pragma unroll
        for (int r = 0; r < BM; r += ROWSTEP) {
            float4 v = *reinterpret_cast<const float4*>(&A[(size_t)(m0 + r + lrow)*K + k0 + lcol]);
            if (bnA) {
                v.x = fmaxf(bnA[k0+lcol+0]*v.x + bnA[K + k0+lcol+0], 0.f);
                v.y = fmaxf(bnA[k0+lcol+1]*v.y + bnA[K + k0+lcol+1], 0.f);
                v.z = fmaxf(bnA[k0+lcol+2]*v.z + bnA[K + k0+lcol+2], 0.f);
                v.w = fmaxf(bnA[k0+lcol+3]*v.w + bnA[K + k0+lcol+3], 0.f);
            }
            As[lcol+0][r+lrow] = v.x; As[lcol+1][r+lrow] = v.y;
            As[lcol+2][r+lrow] = v.z; As[lcol+3][r+lrow] = v.w;
        }
        #pragma unroll
        for (int r = 0; r < BN; r += ROWSTEP) {
            float4 v = *reinterpret_cast<const float4*>(&W[(size_t)(n0 + r + lrow)*K + k0 + lcol]);
            Ws[lcol+0][r+lrow] = v.x; Ws[lcol+1][r+lrow] = v.y;
            Ws[lcol+2][r+lrow] = v.z; Ws[lcol+3][r+lrow] = v.w;
        }
        __syncthreads();
        #pragma unroll
        for (int kk = 0; kk < BK; kk++) {
            float af[TM], wf[TN];
            #pragma unroll
            for (int i = 0; i < TM; i += 4) {
                float4 t = *reinterpret_cast<const float4*>(&As[kk][ty*TM + i]);
                af[i] = t.x; af[i+1] = t.y; af[i+2] = t.z; af[i+3] = t.w;
            }
            #pragma unroll
            for (int j = 0; j < TN; j += 4) {
                float4 t = *reinterpret_cast<const float4*>(&Ws[kk][tx*TN + j]);
                wf[j] = t.x; wf[j+1] = t.y; wf[j+2] = t.z; wf[j+3] = t.w;
            }
            #pragma unroll
            for (int i = 0; i < TM; i++)
                #pragma unroll
                for (int j = 0; j < TN; j++)
                    acc[i][j] = fmaf(af[i], wf[j], acc[i][j]);
        }
        __syncthreads();
    }
    #pragma unroll
    for (int j = 0; j < TN; j++) {
        int n = n0 + tx*TN + j;
        float bsv = bias ? bias[n] : 0.f;
        float s_ = 0.f, q_ = 0.f;
        #pragma unroll
        for (int i = 0; i < TM; i++) {
            float y = acc[i][j] + bsv;
            acc[i][j] = y;
            s_ += y; q_ += y*y;
        }
        atomicAdd(&csum[tx*TN + j], s_);
        atomicAdd(&csq [tx*TN + j], q_);
    }
    #pragma unroll
    for (int i = 0; i < TM; i++) {
        #pragma unroll
        for (int j = 0; j < TN; j += 4) {
            float4 v = make_float4(acc[i][j], acc[i][j+1], acc[i][j+2], acc[i][j+3]);
            *reinterpret_cast<float4*>(&C[(size_t)(m0 + ty*TM + i)*N + n0 + tx*TN + j]) = v;
        }
    }
    __syncthreads();
    if (tid < BN) {
        atomicAdd(&sum[n0 + tid], csum[tid]);
        atomicAdd(&sq [n0 + tid], csq[tid]);
    }
}

// ============ HMMA bf16 split-precision GEMM, 1-sync pipelined ===============
// Output mode: C != nullptr -> full fp32 C store (+rowAdd).
//              C == nullptr -> per-query (32-row group) max/min extremes into
//                              outMax/outMin [M>>5, N]. Stats still computed.
__device__ __forceinline__ void gemm_issue_chunk(
    const __nv_bfloat16* __restrict__ A, const __nv_bfloat16* __restrict__ W,
    size_t m0, int n0, int K, int K2, uint32_t u0, int tid, int ch, int nch)
{
    if (ch < nch) {
        uint32_t sb = u0 + (uint32_t)(ch % 3) * 32768u;
        int k0 = ch * 32;
        #pragma unroll
        for (int i = 0; i < 8; i++) {
            int idx = i * 256 + tid;
            int buf = idx >> 9;
            int r = (idx >> 2) & 127;
            int c16 = idx & 3;
            uint32_t dst = sb + (uint32_t)buf * 8192u
                         + (((uint32_t)(r * 64 + c16 * 16)) ^ (((uint32_t)(r & 6)) << 3));
            const __nv_bfloat16* src;
            if (buf == 0)      src = A + (m0 + r) * K2 + k0 + c16 * 8;
            else if (buf == 1) src = A + (m0 + r) * K2 + K + k0 + c16 * 8;
            else if (buf == 2) src = W + ((size_t)(n0 + r)) * K2 + k0 + c16 * 8;
            else               src = W + ((size_t)(n0 + r)) * K2 + K + k0 + c16 * 8;
            asm volatile("cp.async.cg.shared.global [%0], [%1], 16;" :: "r"(dst), "l"(src));
        }
    }
    asm volatile("cp.async.commit_group;" ::: "memory");
}

extern __shared__ unsigned char dynsm[];

__global__ void __launch_bounds__(256, 2) mma_gemm_kernel(
    const __nv_bfloat16* __restrict__ A, const __nv_bfloat16* __restrict__ W,
    const float* __restrict__ bias, float* __restrict__ C,
    int N, int K, float* __restrict__ gsum, float* __restrict__ gsq,
    const float* __restrict__ rowAdd,
    float* __restrict__ outMax, float* __restrict__ outMin)
{
    float* sbias = (float*)(dynsm + 98304);
    float* csum  = sbias + 128;
    float* csq   = csum + 128;

    int tid = threadIdx.x, wid = tid >> 5, lane = tid & 31;
    int n0 = blockIdx.x * 128;
    size_t m0 = (size_t)blockIdx.y * 128;
    int K2 = 2 * K;
    if (tid < 128) {
        sbias[tid] = bias ? bias[n0 + tid] : 0.f;
        csum[tid] = 0.f; csq[tid] = 0.f;
    }

    int wm = (wid & 1) * 64;
    int wn = (wid >> 1) * 32;

    float acc[4][4][4];
    #pragma unroll
    for (int mi = 0; mi < 4; mi++)
        #pragma unroll
        for (int ni = 0; ni < 4; ni++)
            #pragma unroll
            for (int j = 0; j < 4; j++) acc[mi][ni][j] = 0.f;

    uint32_t u0 = smem_to_u32(dynsm);
    int g = lane >> 3, lr = lane & 7;
    uint32_t sw = ((uint32_t)(lr & 6)) << 3;
    uint32_t arow = (uint32_t)((wm + (g & 1) * 8 + lr) * 64);
    uint32_t acol = (uint32_t)((g >> 1) * 16);
    uint32_t brow = (uint32_t)((wn + (g >> 1) * 8 + lr) * 64);
    uint32_t bcol = (uint32_t)((g & 1) * 16);

    const int nch = K >> 5;
    gemm_issue_chunk(A, W, m0, n0, K, K2, u0, tid, 0, nch);
    gemm_issue_chunk(A, W, m0, n0, K, K2, u0, tid, 1, nch);

    for (int ch = 0; ch < nch; ch++) {
        asm volatile("cp.async.wait_group 1;" ::: "memory");
        __syncthreads();
        gemm_issue_chunk(A, W, m0, n0, K, K2, u0, tid, ch + 2, nch);
        uint32_t sb = u0 + (uint32_t)(ch % 3) * 32768u;
        #pragma unroll
        for (int kk = 0; kk < 2; kk++) {
            uint32_t kb = (uint32_t)(kk * 32);
            uint32_t af_hi[4][4], bf_hi[2][4];
            #pragma unroll
            for (int mi = 0; mi < 4; mi++)
                ldsm4(af_hi[mi], sb + arow + (uint32_t)(mi * 1024) + ((kb + acol) ^ sw));
            #pragma unroll
            for (int bi = 0; bi < 2; bi++)
                ldsm4(bf_hi[bi], sb + 16384u + brow + (uint32_t)(bi * 1024) + ((kb + bcol) ^ sw));
            #pragma unroll
            for (int mi = 0; mi < 4; mi++)
                #pragma unroll
                for (int ni = 0; ni < 4; ni++)
                    mma_bf16(acc[mi][ni], af_hi[mi],
                             bf_hi[ni >> 1][(ni & 1) * 2], bf_hi[ni >> 1][(ni & 1) * 2 + 1]);
            {
                uint32_t bf_lo[2][4];
                #pragma unroll
                for (int bi = 0; bi < 2; bi++)
                    ldsm4(bf_lo[bi], sb + 24576u + brow + (uint32_t)(bi * 1024) + ((kb + bcol) ^ sw));
                #pragma unroll
                for (int mi = 0; mi < 4; mi++)
                    #pragma unroll
                    for (int ni = 0; ni < 4; ni++)
                        mma_bf16(acc[mi][ni], af_hi[mi],
                                 bf_lo[ni >> 1][(ni & 1) * 2], bf_lo[ni >> 1][(ni & 1) * 2 + 1]);
            }
            {
                uint32_t af_lo[4][4];
                #pragma unroll
                for (int mi = 0; mi < 4; mi++)
                    ldsm4(af_lo[mi], sb + 8192u + arow + (uint32_t)(mi * 1024) + ((kb + acol) ^ sw));
                #pragma unroll
                for (int mi = 0; mi < 4; mi++)
                    #pragma unroll
                    for (int ni = 0; ni < 4; ni++)
                        mma_bf16(acc[mi][ni], af_lo[mi],
                                 bf_hi[ni >> 1][(ni & 1) * 2], bf_hi[ni >> 1][(ni & 1) * 2 + 1]);
            }
        }
    }
    __syncthreads();

    int r = lane >> 2, c2 = (lane & 3) << 1;
    float cs[8], cq[8];
    #pragma unroll
    for (int s = 0; s < 8; s++) { cs[s] = 0.f; cq[s] = 0.f; }

    if (C) {
        // full-store path (+rowAdd)
        #pragma unroll
        for (int mi = 0; mi < 4; mi++) {
            #pragma unroll
            for (int ni = 0; ni < 4; ni++) {
                int col = wn + ni * 8 + c2;
                float b0v = sbias[col], b1v = sbias[col + 1];
                size_t row = m0 + wm + mi * 16 + r;
                float a00 = 0.f, a01 = 0.f, a10 = 0.f, a11 = 0.f;
                if (rowAdd) {
                    const float* r0p = rowAdd + (row >> 5) * (size_t)N + n0 + col;
                    const float* r1p = rowAdd + ((row + 8) >> 5) * (size_t)N + n0 + col;
                    a00 = r0p[0]; a01 = r0p[1];
                    a10 = r1p[0]; a11 = r1p[1];
                }
                float v00 = acc[mi][ni][0] + b0v + a00, v01 = acc[mi][ni][1] + b1v + a01;
                float v10 = acc[mi][ni][2] + b0v + a10, v11 = acc[mi][ni][3] + b1v + a11;
                *reinterpret_cast<float2*>(&C[row * (size_t)N + n0 + col]) = make_float2(v00, v01);
                *reinterpret_cast<float2*>(&C[(row + 8) * (size_t)N + n0 + col]) = make_float2(v10, v11);
                cs[ni*2]   += v00 + v10;  cs[ni*2+1] += v01 + v11;
                cq[ni*2]   += v00*v00 + v10*v10;
                cq[ni*2+1] += v01*v01 + v11*v11;
            }
        }
    } else {
        // extremes path: per-query (32 rows) max/min; warp half-tile = 2 queries
        #pragma unroll
        for (int pair = 0; pair < 2; pair++) {
            size_t qrow = ((m0 + (size_t)wm) >> 5) + (size_t)pair;
            #pragma unroll
            for (int ni = 0; ni < 4; ni++) {
                int col = wn + ni * 8 + c2;
                float b0v = sbias[col], b1v = sbias[col + 1];
                float mx0 = -3.4e38f, mx1 = -3.4e38f, mn0 = 3.4e38f, mn1 = 3.4e38f;
                #pragma unroll
                for (int mm = 0; mm < 2; mm++) {
                    int mi = pair * 2 + mm;
                    float v00 = acc[mi][ni][0] + b0v, v01 = acc[mi][ni][1] + b1v;
                    float v10 = acc[mi][ni][2] + b0v, v11 = acc[mi][ni][3] + b1v;
                    mx0 = fmaxf(mx0, fmaxf(v00, v10)); mn0 = fminf(mn0, fminf(v00, v10));
                    mx1 = fmaxf(mx1, fmaxf(v01, v11)); mn1 = fminf(mn1, fminf(v01, v11));
                    cs[ni*2]   += v00 + v10;  cs[ni*2+1] += v01 + v11;
                    cq[ni*2]   += v00*v00 + v10*v10;
                    cq[ni*2+1] += v01*v01 + v11*v11;
                }
                #pragma unroll
                for (int o = 4; o <= 16; o <<= 1) {
                    mx0 = fmaxf(mx0, __shfl_xor_sync(0xffffffffu, mx0, o));
                    mx1 = fmaxf(mx1, __shfl_xor_sync(0xffffffffu, mx1, o));
                    mn0 = fminf(mn0, __shfl_xor_sync(0xffffffffu, mn0, o));
                    mn1 = fminf(mn1, __shfl_xor_sync(0xffffffffu, mn1, o));
                }
                if (lane < 4) {
                    size_t off = qrow * (size_t)N + n0 + wn + ni * 8 + lane * 2;
                    *reinterpret_cast<float2*>(&outMax[off]) = make_float2(mx0, mx1);
                    *reinterpret_cast<float2*>(&outMin[off]) = make_float2(mn0, mn1);
                }
            }
        }
    }
    if (gsum) {
        #pragma unroll
        for (int s = 0; s < 8; s++) {
            float v = cs[s], q = cq[s];
            #pragma unroll
            for (int o = 4; o <= 16; o <<= 1) {
                v += __shfl_xor_sync(0xffffffffu, v, o);
                q += __shfl_xor_sync(0xffffffffu, q, o);
            }
            if (lane < 4) {
                int col = wn + (s >> 1) * 8 + lane * 2 + (s & 1);
                atomicAdd(&csum[col], v);
                atomicAdd(&csq[col], q);
            }
        }
        __syncthreads();
        if (tid < 128) {
            atomicAdd(&gsum[n0 + tid], csum[tid]);
            atomicAdd(&gsq [n0 + tid], csq[tid]);
        }
    }
}

// ---------------- FPS (float4-packed, float-max + ballot index recovery) -----
__global__ void __launch_bounds__(1024) fps_kernel(
    const float* __restrict__ xyz, int N, int S,
    int* __restrict__ idx_out, float* __restrict__ xyz_out)
{
    __shared__ float4 pnt[2048];
    __shared__ float rv[32];
    __shared__ int   ri[32];
    __shared__ int   selv;
    __shared__ int   sidx[512];
    int b = blockIdx.x, tid = threadIdx.x, lane = tid & 31, wid = tid >> 5;
    for (int i = tid; i < N; i += 1024) {
        float4 p;
        p.x = xyz[(b*N + i)*3 + 0];
        p.y = xyz[(b*N + i)*3 + 1];
        p.z = xyz[(b*N + i)*3 + 2];
        p.w = 1e10f;
        pnt[i] = p;
    }
    __syncthreads();
    int sel = 0;
    for (int it = 0; it < S; it++) {
        if (tid == 0) sidx[it] = sel;
        float4 sp = pnt[sel];
        float bv = -1.f; int bi = 0;
        for (int j = tid; j < N; j += 1024) {
            float4 p = pnt[j];
            float dx = p.x - sp.x, dy = p.y - sp.y, dz = p.z - sp.z;
            float d = dx*dx + dy*dy + dz*dz;
            float nd = fminf(p.w, d);
            pnt[j].w = nd;
            if (nd > bv) { bv = nd; bi = j; }
        }
        float mv = bv;
        #pragma unroll
        for (int o = 16; o > 0; o >>= 1)
            mv = fmaxf(mv, __shfl_xor_sync(0xffffffffu, mv, o));
        unsigned bal = __ballot_sync(0xffffffffu, bv == mv);
        int src = __ffs(bal) - 1;
        int bw = __shfl_sync(0xffffffffu, bi, src);
        if (lane == 0) { rv[wid] = mv; ri[wid] = bw; }
        __syncthreads();
        if (tid < 32) {
            float v = rv[lane];
            int  ii = ri[lane];
            float vm = v;
            #pragma unroll
            for (int o = 16; o > 0; o >>= 1)
                vm = fmaxf(vm, __shfl_xor_sync(0xffffffffu, vm, o));
            unsigned b2 = __ballot_sync(0xffffffffu, v == vm);
            int s2 = __ffs(b2) - 1;
            int w = __shfl_sync(0xffffffffu, ii, s2);
            if (lane == 0) selv = w;
        }
        __syncthreads();
        sel = selv;
    }
    for (int s = tid; s < S; s += 1024) {
        int i = sidx[s];
        float4 p = pnt[i];
        idx_out[b*S + s] = i;
        xyz_out[(b*S + s)*3 + 0] = p.x;
        xyz_out[(b*S + s)*3 + 1] = p.y;
        xyz_out[(b*S + s)*3 + 2] = p.z;
    }
}

// ---------------- kNN (k=32) -------------------------------------------------
__global__ void knn_kernel(const float* __restrict__ q_xyz, const float* __restrict__ c_xyz,
                           int S, int N, int* __restrict__ knn)
{
    __shared__ float cx[2048], cy[2048], cz[2048];
    int b = blockIdx.y, tid = threadIdx.x;
    for (int i = tid; i < N; i += blockDim.x) {
        cx[i] = c_xyz[(b*N + i)*3 + 0];
        cy[i] = c_xyz[(b*N + i)*3 + 1];
        cz[i] = c_xyz[(b*N + i)*3 + 2];
    }
    __syncthreads();
    int warp = tid >> 5, lane = tid & 31;
    int q = blockIdx.x * (blockDim.x >> 5) + warp;
    if (q >= S) return;
    float qx = q_xyz[(b*S+q)*3+0], qy = q_xyz[(b*S+q)*3+1], qz = q_xyz[(b*S+q)*3+2];
    float topd = 3.4e38f; int topi = 0;
    float curmax = 3.4e38f;
    for (int c0 = 0; c0 < N; c0 += 32) {
        int c = c0 + lane;
        float dx = cx[c]-qx, dy = cy[c]-qy, dz = cz[c]-qz;
        float d = dx*dx + dy*dy + dz*dz;
        unsigned bal = __ballot_sync(0xffffffffu, d < curmax);
        while (bal) {
            int src = __ffs(bal) - 1; bal &= bal - 1;
            float dv = __shfl_sync(0xffffffffu, d, src);
            float mv = topd; int ml = lane;
            #pragma unroll
            for (int off = 16; off > 0; off >>= 1) {
                float ov = __shfl_xor_sync(0xffffffffu, mv, off);
                int   ol = __shfl_xor_sync(0xffffffffu, ml, off);
                if (ov > mv || (ov == mv && ol < ml)) { mv = ov; ml = ol; }
            }
            if (dv < mv && lane == ml) { topd = dv; topi = c0 + src; }
            curmax = mv;
        }
    }
    knn[(b*S + q)*32 + lane] = topi;
}

// ---------------- gathers (rel-only rows + separate ctr buffer) --------------
__global__ void gather1_kernel(const float* __restrict__ f1raw, const int* __restrict__ fps,
                               const int* __restrict__ knn, const float* __restrict__ ab,
                               __nv_bfloat16* __restrict__ relA, __nv_bfloat16* __restrict__ ctrA)
{
    int bs = blockIdx.x;           // b*512+s
    int b = bs >> 9;
    __shared__ float ctr[64];
    int tid = threadIdx.x;
    if (tid < 64) {
        int ci = fps[bs];
        float v = f1raw[(size_t)(b*2048 + ci)*64 + tid];
        v = fmaxf(ab[tid]*v + ab[64+tid], 0.f);
        ctr[tid] = v;
        __nv_bfloat16 h, l; split2(v, h, l);
        ctrA[(size_t)bs*128 + tid] = h;
        ctrA[(size_t)bs*128 + 64 + tid] = l;
    }
    __syncthreads();
    for (int e = tid; e < 32*64; e += 256) {
        int k = e >> 6, c = e & 63;
        int ni = knn[bs*32 + k];
        float v = f1raw[(size_t)(b*2048 + ni)*64 + c];
        v = fmaxf(ab[c]*v + ab[64+c], 0.f) - ctr[c];
        __nv_bfloat16 h, l; split2(v, h, l);
        __nv_bfloat16* p = relA + ((size_t)bs*32 + k) * 128;
        p[c] = h;
        p[64 + c] = l;
    }
}

__global__ void gather2_kernel(const float* __restrict__ feat, const int* __restrict__ fps,
                               const int* __restrict__ knn,
                               __nv_bfloat16* __restrict__ relA, __nv_bfloat16* __restrict__ ctrA)
{
    int bs = blockIdx.x;           // b*256+s
    int b = bs >> 8;
    __shared__ float ctr[128];
    int tid = threadIdx.x;
    if (tid < 128) {
        int ci = fps[bs];
        float v = feat[(size_t)(b*512 + ci)*128 + tid];
        ctr[tid] = v;
        __nv_bfloat16 h, l; split2(v, h, l);
        ctrA[(size_t)bs*256 + tid] = h;
        ctrA[(size_t)bs*256 + 128 + tid] = l;
    }
    __syncthreads();
    for (int e = tid; e < 32*128; e += 256) {
        int k = e >> 7, c = e & 127;
        int ni = knn[bs*32 + k];
        float v = feat[(size_t)(b*512 + ni)*128 + c] - ctr[c];
        __nv_bfloat16 h, l; split2(v, h, l);
        __nv_bfloat16* p = relA + ((size_t)bs*32 + k) * 256;
        p[c] = h;
        p[128 + c] = l;
    }
}

// BN+ReLU + hi/lo split of a raw GEMM output: X[M,C] -> O[M,2C]
__global__ void split_bn_kernel(const float* __restrict__ X, const float* __restrict__ ab,
                                __nv_bfloat16* __restrict__ O, int C, int total_half)
{
    int i = blockIdx.x * 256 + threadIdx.x;
    if (i >= total_half) return;
    int hc = C >> 1;
    int row = i / hc;
    int c = (i - row * hc) * 2;
    float2 v = *reinterpret_cast<const float2*>(&X[(size_t)row * C + c]);
    float y0 = fmaxf(ab[c]   * v.x + ab[C + c],     0.f);
    float y1 = fmaxf(ab[c+1] * v.y + ab[C + c + 1], 0.f);
    __nv_bfloat16 h0, l0, h1, l1;
    split2(y0, h0, l0); split2(y1, h1, l1);
    __nv_bfloat162 hh; hh.x = h0; hh.y = h1;
    __nv_bfloat162 ll; ll.x = l0; ll.y = l1;
    *reinterpret_cast<__nv_bfloat162*>(&O[(size_t)row * 2 * C + c]) = hh;
    *reinterpret_cast<__nv_bfloat162*>(&O[(size_t)row * 2 * C + C + c]) = ll;
}

// weight split fp32 [N,K] -> bf16 [N,2K] = [hi|lo]
__global__ void wsplit_kernel(const float* __restrict__ W, __nv_bfloat16* __restrict__ O,
                              int K, int total)
{
    int i = blockIdx.x * 256 + threadIdx.x;
    if (i >= total) return;
    int row = i / K, c = i - row * K;
    __nv_bfloat16 h, l; split2(W[i], h, l);
    O[(size_t)row * 2 * K + c] = h;
    O[(size_t)row * 2 * K + K + c] = l;
}

// weight pair split: W [N, K] with K = 2*Khalf = [rel|ctr] columns
__global__ void wsplit_pair_kernel(const float* __restrict__ W,
                                   __nv_bfloat16* __restrict__ Wr,
                                   __nv_bfloat16* __restrict__ Wc,
                                   int K, int Khalf, int total)
{
    int i = blockIdx.x * 256 + threadIdx.x;
    if (i >= total) return;
    int row = i / K, c = i - row * K;
    __nv_bfloat16 h, l; split2(W[i], h, l);
    if (c < Khalf) {
        Wr[(size_t)row * 2 * Khalf + c] = h;
        Wr[(size_t)row * 2 * Khalf + Khalf + c] = l;
    } else {
        int cc = c - Khalf;
        Wc[(size_t)row * 2 * Khalf + cc] = h;
        Wc[(size_t)row * 2 * Khalf + Khalf + cc] = l;
    }
}

// BN+relu over precomputed per-query extremes -> feat1 [q, C]
__global__ void ext_bn_kernel(const float* __restrict__ mx, const float* __restrict__ mn,
                              const float* __restrict__ ab, float* __restrict__ outF,
                              int C, int total)
{
    int idx = blockIdx.x * 256 + threadIdx.x;
    if (idx >= total) return;
    int o = idx % C;
    float a = ab[o];
    float e = (a >= 0.f) ? mx[idx] : mn[idx];
    outF[idx] = fmaxf(a * e + ab[C + o], 0.f);
}

// final: BN+relu over extremes + transpose to [B, 512, 256]
__global__ void ext_final_kernel(const float* __restrict__ mx, const float* __restrict__ mn,
                                 const float* __restrict__ ab, float* __restrict__ out)
{
    int idx = blockIdx.x * 256 + threadIdx.x;  // 16*256*512
    int o = idx & 511; int q = idx >> 9; int b = q >> 8, s = q & 255;
    size_t off = (size_t)q * 512 + o;
    float a = ab[o];
    float e = (a >= 0.f) ? mx[off] : mn[off];
    out[(size_t)(b*512 + o)*256 + s] = fmaxf(a * e + ab[512 + o], 0.f);
}

// ============================ driver =========================================
extern "C" void kernel_launch(void* const* d_in, const int* in_sizes, int n_in,
                              void* d_out, int out_size)
{
    const float* x       = (const float*)d_in[0];
    const float* emb_w1  = (const float*)d_in[1];
    const float* emb_g1  = (const float*)d_in[2];
    const float* emb_b1  = (const float*)d_in[3];
    const float* emb_w2  = (const float*)d_in[4];
    const float* emb_g2  = (const float*)d_in[5];
    const float* emb_b2  = (const float*)d_in[6];
    const float* sg1_w1  = (const float*)d_in[7];
    const float* sg1_cb1 = (const float*)d_in[8];
    const float* sg1_g1  = (const float*)d_in[9];
    const float* sg1_b1  = (const float*)d_in[10];
    const float* sg1_w2  = (const float*)d_in[11];
    const float* sg1_cb2 = (const float*)d_in[12];
    const float* sg1_g2  = (const float*)d_in[13];
    const float* sg1_b2  = (const float*)d_in[14];
    const float* sg2_w1  = (const float*)d_in[15];
    const float* sg2_cb1 = (const float*)d_in[16];
    const float* sg2_g1  = (const float*)d_in[17];
    const float* sg2_b1  = (const float*)d_in[18];
    const float* sg2_w2  = (const float*)d_in[19];
    const float* sg2_cb2 = (const float*)d_in[20];
    const float* sg2_g2  = (const float*)d_in[21];
    const float* sg2_b2  = (const float*)d_in[22];
    float* out = (float*)d_out;

    float *xyz, *xyz1, *xyz2, *f0, *f1r, *feat1, *sum, *sq, *ab, *bufA, *bufB, *ctrY;
    float *extM, *extN;
    __nv_bfloat16 *wbuf, *ctrA;
    int *fps1, *fps2, *knn1, *knn2;
    cudaGetSymbolAddress((void**)&xyz,   g_xyz);
    cudaGetSymbolAddress((void**)&xyz1,  g_xyz1);
    cudaGetSymbolAddress((void**)&xyz2,  g_xyz2);
    cudaGetSymbolAddress((void**)&f0,    g_f0);
    cudaGetSymbolAddress((void**)&f1r,   g_f1r);
    cudaGetSymbolAddress((void**)&feat1, g_feat1);
    cudaGetSymbolAddress((void**)&sum,   g_sum);
    cudaGetSymbolAddress((void**)&sq,    g_sq);
    cudaGetSymbolAddress((void**)&ab,    g_ab);
    cudaGetSymbolAddress((void**)&bufA,  g_bufA);
    cudaGetSymbolAddress((void**)&bufB,  g_bufB);
    cudaGetSymbolAddress((void**)&wbuf,  g_wbuf);
    cudaGetSymbolAddress((void**)&ctrA,  g_ctrA);
    cudaGetSymbolAddress((void**)&ctrY,  g_ctrY);
    cudaGetSymbolAddress((void**)&extM,  g_extM);
    cudaGetSymbolAddress((void**)&extN,  g_extN);
    cudaGetSymbolAddress((void**)&fps1,  g_fps1);
    cudaGetSymbolAddress((void**)&fps2,  g_fps2);
    cudaGetSymbolAddress((void**)&knn1,  g_knn1);
    cudaGetSymbolAddress((void**)&knn2,  g_knn2);

    cudaFuncSetAttribute(mma_gemm_kernel,
                         cudaFuncAttributeMaxDynamicSharedMemorySize, 99840);
    const int DSM = 99840;

    cudaStream_t s_side;
    cudaStreamCreateWithFlags(&s_side, cudaStreamNonBlocking);
    cudaEvent_t ev0, ev1, ev2;
    cudaEventCreateWithFlags(&ev0, cudaEventDisableTiming);
    cudaEventCreateWithFlags(&ev1, cudaEventDisableTiming);
    cudaEventCreateWithFlags(&ev2, cudaEventDisableTiming);

    __nv_bfloat16* bA = (__nv_bfloat16*)bufA;
    __nv_bfloat16* wr = wbuf;
    __nv_bfloat16* wc = wbuf + 262144;

    // ---- transpose, then fork geometry pipeline onto side stream ----
    transpose_xyz_kernel<<<128, 256>>>(x, xyz);
    cudaEventRecord(ev0, 0);
    cudaStreamWaitEvent(s_side, ev0, 0);
    fps_kernel<<<16, 1024, 0, s_side>>>(xyz, 2048, 512, fps1, xyz1);
    knn_kernel<<<dim3(64, 16), 256, 0, s_side>>>(xyz1, xyz, 512, 2048, knn1);
    cudaEventRecord(ev1, s_side);
    fps_kernel<<<16, 1024, 0, s_side>>>(xyz1, 512, 256, fps2, xyz2);
    knn_kernel<<<dim3(32, 16), 256, 0, s_side>>>(xyz2, xyz1, 256, 512, knn2);
    cudaEventRecord(ev2, s_side);

    // ---- embedding (main stream, concurrent with fps/knn) ----
    zero_kernel<<<1, 512>>>(sum, sq, 512);
    emb1_kernel<<<128, 256>>>(x, emb_w1, f0, sum, sq);
    bn_finalize<<<1, 512>>>(sum, sq, emb_g1, emb_b1, 1.f/32768.f, 64, ab);
    gemm_bn_kernel<128,64,16,8,4><<<dim3(256, 1), 256>>>(f0, emb_w2, nullptr, ab, f1r,
                                                         32768, 64, 64, sum, sq);
    bn_finalize<<<1, 512>>>(sum, sq, emb_g2, emb_b2, 1.f/32768.f, 64, ab);

    // ---- stage 1 (needs fps1/knn1) ----
    cudaStreamWaitEvent(0, ev1, 0);
    gather1_kernel<<<8192, 256>>>(f1r, fps1, knn1, ab, bA, ctrA);
    wsplit_pair_kernel<<<64, 256>>>(sg1_w1, wr, wc, 128, 64, 128*128);
    mma_gemm_kernel<<<dim3(1, 64), 256, DSM>>>(ctrA, wc, nullptr, ctrY, 128, 64,
                                               nullptr, nullptr, nullptr, nullptr, nullptr);
    mma_gemm_kernel<<<dim3(1, 2048), 256, DSM>>>(bA, wr, sg1_cb1, bufB, 128, 64,
                                                 sum, sq, ctrY, nullptr, nullptr);
    bn_finalize<<<1, 512>>>(sum, sq, sg1_g1, sg1_b1, 1.f/262144.f, 128, ab);
    split_bn_kernel<<<65536, 256>>>(bufB, ab, bA, 128, 16777216);
    wsplit_kernel<<<64, 256>>>(sg1_w2, wbuf, 128, 128*128);
    mma_gemm_kernel<<<dim3(1, 2048), 256, DSM>>>(bA, wbuf, sg1_cb2, nullptr, 128, 128,
                                                 sum, sq, nullptr, extM, extN);
    bn_finalize<<<1, 512>>>(sum, sq, sg1_g2, sg1_b2, 1.f/262144.f, 128, ab);
    ext_bn_kernel<<<4096, 256>>>(extM, extN, ab, feat1, 128, 1048576);

    // ---- stage 2 (needs fps2/knn2) ----
    cudaStreamWaitEvent(0, ev2, 0);
    gather2_kernel<<<4096, 256>>>(feat1, fps2, knn2, bA, ctrA);
    wsplit_pair_kernel<<<512, 256>>>(sg2_w1, wr, wc, 256, 128, 512*256);
    mma_gemm_kernel<<<dim3(4, 32), 256, DSM>>>(ctrA, wc, nullptr, ctrY, 512, 128,
                                               nullptr, nullptr, nullptr, nullptr, nullptr);
    mma_gemm_kernel<<<dim3(4, 1024), 256, DSM>>>(bA, wr, sg2_cb1, bufB, 512, 128,
                                                 sum, sq, ctrY, nullptr, nullptr);
    bn_finalize<<<1, 512>>>(sum, sq, sg2_g1, sg2_b1, 1.f/131072.f, 512, ab);
    split_bn_kernel<<<131072, 256>>>(bufB, ab, bA, 512, 33554432);
    wsplit_kernel<<<1024, 256>>>(sg2_w2, wbuf, 512, 512*512);
    mma_gemm_kernel<<<dim3(4, 1024), 256, DSM>>>(bA, wbuf, sg2_cb2, nullptr, 512, 512,
                                                 sum, sq, nullptr, extM, extN);
    bn_finalize<<<1, 512>>>(sum, sq, sg2_g2, sg2_b2, 1.f/131072.f, 512, ab);
    ext_final_kernel<<<8192, 256>>>(extM, extN, ab, out);
}